// round 3
// baseline (speedup 1.0000x reference)
#include <cuda_runtime.h>
#include <math.h>

#define Bq 8
#define Nn 512
#define NFEAT 32
#define NHID 128
#define NHEADS 4
#define MROWS (Bq*Nn)   // 4096

// ---------------- scratch (device globals; no allocation) ----------------
__device__ __align__(256) float g_bufA[MROWS*NHID];
__device__ __align__(256) float g_bufB[MROWS*NHID];
__device__ __align__(256) float g_tmp [MROWS*2*NHID];
__device__ __align__(256) float g_hp2 [MROWS*NHEADS*NHID];          // [b,n,H*o]
__device__ __align__(256) float g_Wh  [NHEADS*Bq*Nn*NHID];          // [z,n,o]
__device__ __align__(256) float g_hf  [MROWS*NHID];
__device__ __align__(256) float g_ht  [MROWS*NHID];
__device__ __align__(256) unsigned g_mask [Bq*Nn*(Nn/32)];
__device__ __align__(256) unsigned g_maskT[Bq*Nn*(Nn/32)];

// ---------------- batched-offset descriptor ----------------
struct BOff { int mod; long inS; long outS; };
__device__ __forceinline__ long boff(BOff o, int z){
    return (long)(z % o.mod) * o.inS + (long)(z / o.mod) * o.outS;
}

// ---------------- generic batched GEMM: C = act(A @ W + bias) ----------------
// Tile 64x64x16, 256 thr, 4x4 micro, register-staged double buffering.
template<int ACT>   // 0=none 1=lrelu(0.01) 2=elu
__global__ void __launch_bounds__(256) gemm_k(
    const float* __restrict__ A, BOff ao, int ldA,
    const float* __restrict__ W, BOff wo, int ldW,
    const float* __restrict__ bias, BOff bo,
    float* __restrict__ C, BOff co, int ldC,
    int K)
{
    int z = blockIdx.z;
    A += boff(ao, z); W += boff(wo, z); C += boff(co, z);
    if (bias) bias += boff(bo, z);

    __shared__ float As[16][68];
    __shared__ float Bs[16][68];

    int tid = threadIdx.x;
    int tx = tid & 15, ty = tid >> 4;
    int m0 = blockIdx.y * 64, n0 = blockIdx.x * 64;
    int arow = tid >> 2, acg = tid & 3;
    int brow = tid >> 4, bcg = tid & 15;

    float acc[4][4] = {};

    const float* aptr = &A[(long)(m0 + arow) * ldA + acg * 4];
    const float* bptr = &W[(long)brow * ldW + n0 + bcg * 4];
    float4 av = *(const float4*)aptr;
    float4 bv = *(const float4*)bptr;

    for (int k0 = 0; k0 < K; k0 += 16) {
        As[acg*4+0][arow] = av.x; As[acg*4+1][arow] = av.y;
        As[acg*4+2][arow] = av.z; As[acg*4+3][arow] = av.w;
        *(float4*)&Bs[brow][bcg*4] = bv;
        __syncthreads();
        if (k0 + 16 < K) {
            av = *(const float4*)(aptr + k0 + 16);
            bv = *(const float4*)(bptr + (long)(k0 + 16) * ldW);
        }
        #pragma unroll
        for (int kk = 0; kk < 16; kk++) {
            float4 af = *(const float4*)&As[kk][ty*4];
            float4 bf = *(const float4*)&Bs[kk][tx*4];
            float a_[4] = {af.x, af.y, af.z, af.w};
            float b_[4] = {bf.x, bf.y, bf.z, bf.w};
            #pragma unroll
            for (int i = 0; i < 4; i++)
                #pragma unroll
                for (int j = 0; j < 4; j++)
                    acc[i][j] = fmaf(a_[i], b_[j], acc[i][j]);
        }
        __syncthreads();
    }

    #pragma unroll
    for (int i = 0; i < 4; i++) {
        int m = m0 + ty * 4 + i;
        #pragma unroll
        for (int j = 0; j < 4; j++) {
            int n = n0 + tx * 4 + j;
            float v = acc[i][j];
            if (bias) v += bias[n];
            if (ACT == 1) v = v > 0.f ? v : 0.01f * v;
            else if (ACT == 2) v = v > 0.f ? v : (expf(v) - 1.f);
            C[(long)m * ldC + n] = v;
        }
    }
}

// ---------------- fused GAT aggregate ----------------
// out = act( softmax_row(mask, lrelu(s1 s2^T)) @ Wh ),  s1/s2 computed in-kernel.
// Block: 64 rows (i) x 128 cols (o) for one z. grid = (8, Zc). 256 threads.
template<int ACT>   // 1=lrelu 2=elu
__global__ void __launch_bounds__(256) gatagg_k(
    const float* __restrict__ Wh,       // + z*Nn*NHID
    const float* __restrict__ a_base,   // per-head 256 floats (h = z/Bq)
    const unsigned* __restrict__ maskbits,  // [b,i,16]
    float* __restrict__ out, BOff co, int ldC)
{
    int z = blockIdx.y;
    int b = z % Bq, h = z / Bq;
    const float* whz = Wh + (long)z * Nn * NHID;
    const float* a = a_base + h * 256;
    float* outz = out + boff(co, z);
    int i0 = blockIdx.x * 64;

    __shared__ float s1s[Nn];
    __shared__ float s2s[Nn];
    __shared__ float mI[64], zI[64];
    __shared__ unsigned mw[64][16];
    __shared__ float As[16][68];     // [jj][ii]
    __shared__ float Bs[16][132];    // [jj][o]

    int tid = threadIdx.x;
    int lane = tid & 31, warp = tid >> 5;

    // ---- phase 0: mask rows for our 64 i-rows ----
    for (int t = tid; t < 64 * 16; t += 256)
        mw[t >> 4][t & 15] = maskbits[((long)b * Nn + i0 + (t >> 4)) * 16 + (t & 15)];

    // ---- phase 1: s1/s2 for all 512 rows (warp per row) ----
    {
        float4 a1 = *(const float4*)&a[lane * 4];
        float4 a2 = *(const float4*)&a[128 + lane * 4];
        for (int r = warp; r < Nn; r += 8) {
            float4 wv = *(const float4*)&whz[(long)r * NHID + lane * 4];
            float d1 = wv.x*a1.x + wv.y*a1.y + wv.z*a1.z + wv.w*a1.w;
            float d2 = wv.x*a2.x + wv.y*a2.y + wv.z*a2.z + wv.w*a2.w;
            #pragma unroll
            for (int off = 16; off; off >>= 1) {
                d1 += __shfl_xor_sync(~0u, d1, off);
                d2 += __shfl_xor_sync(~0u, d2, off);
            }
            if (!lane) { s1s[r] = d1; s2s[r] = d2; }
        }
    }
    __syncthreads();

    // ---- phase 2: per-row softmax stats (4 threads / row) ----
    {
        int ii = tid >> 2, part = tid & 3;
        float s1i = s1s[i0 + ii];
        float m = -1e30f;
        int jb = part * 128;
        for (int j = jb; j < jb + 128; j++) {
            if ((mw[ii][j >> 5] >> (j & 31)) & 1) {
                float v = s1i * s2s[j];
                v = v > 0.f ? v : 0.01f * v;
                m = fmaxf(m, v);
            }
        }
        m = fmaxf(m, __shfl_xor_sync(~0u, m, 1));
        m = fmaxf(m, __shfl_xor_sync(~0u, m, 2));
        if (m < -1e29f) m = 0.f;
        float s = 0.f;
        for (int j = jb; j < jb + 128; j++) {
            if ((mw[ii][j >> 5] >> (j & 31)) & 1) {
                float v = s1i * s2s[j];
                v = v > 0.f ? v : 0.01f * v;
                s += __expf(v - m);
            }
        }
        s += __shfl_xor_sync(~0u, s, 1);
        s += __shfl_xor_sync(~0u, s, 2);
        if (part == 0) { mI[ii] = m; zI[ii] = s > 0.f ? 1.f / s : 0.f; }
    }
    __syncthreads();

    // ---- phase 3: weighted aggregation (64x128 tile, K=512 in steps of 16) ----
    int tx = tid & 15, ty = tid >> 4;     // cols tx*8..+7, rows ty*4..+3
    int fii = tid & 63, fjb = (tid >> 6) * 4;
    int brow = tid >> 4, bcg = tid & 15;
    float acc[4][8] = {};

    for (int j0 = 0; j0 < Nn; j0 += 16) {
        // generate att tile As[jj][ii]
        float s1i = s1s[i0 + fii];
        float mi = mI[fii], zi = zI[fii];
        #pragma unroll
        for (int q = 0; q < 4; q++) {
            int jj = fjb + q, j = j0 + jj;
            float v = s1i * s2s[j];
            v = v > 0.f ? v : 0.01f * v;
            bool ok = (mw[fii][j >> 5] >> (j & 31)) & 1;
            As[jj][fii] = ok ? __expf(v - mi) * zi : 0.f;
        }
        // load Wh tile Bs[jj][o]
        const float* wr = &whz[(long)(j0 + brow) * NHID];
        *(float4*)&Bs[brow][bcg*4]      = *(const float4*)&wr[bcg*4];
        *(float4*)&Bs[brow][64 + bcg*4] = *(const float4*)&wr[64 + bcg*4];
        __syncthreads();
        #pragma unroll
        for (int kk = 0; kk < 16; kk++) {
            float4 af = *(const float4*)&As[kk][ty*4];
            float a_[4] = {af.x, af.y, af.z, af.w};
            float4 b0 = *(const float4*)&Bs[kk][tx*8];
            float4 b1 = *(const float4*)&Bs[kk][tx*8+4];
            float b_[8] = {b0.x,b0.y,b0.z,b0.w,b1.x,b1.y,b1.z,b1.w};
            #pragma unroll
            for (int i = 0; i < 4; i++)
                #pragma unroll
                for (int j = 0; j < 8; j++)
                    acc[i][j] = fmaf(a_[i], b_[j], acc[i][j]);
        }
        __syncthreads();
    }

    #pragma unroll
    for (int i = 0; i < 4; i++) {
        int m = i0 + ty * 4 + i;
        float vout[8];
        #pragma unroll
        for (int j = 0; j < 8; j++) {
            float v = acc[i][j];
            if (ACT == 1) v = v > 0.f ? v : 0.01f * v;
            else if (ACT == 2) v = v > 0.f ? v : (__expf(v) - 1.f);
            vout[j] = v;
        }
        *(float4*)&outz[(long)m * ldC + tx*8]     = *(float4*)&vout[0];
        *(float4*)&outz[(long)m * ldC + tx*8 + 4] = *(float4*)&vout[4];
    }
}

// ---------------- adjacency -> packed bitmask (normal + transposed) ----------------
__global__ void maskbuild_k(const int* __restrict__ adj,
                            unsigned* __restrict__ mb, unsigned* __restrict__ mbT)
{
    int i = blockIdx.x, b = blockIdx.y, j = threadIdx.x;
    int lane = j & 31, w = j >> 5;
    unsigned bit  = adj[((long)b * Nn + i) * Nn + j] > 0;
    unsigned word = __ballot_sync(~0u, bit);
    if (!lane) mb[((long)b * Nn + i) * 16 + w] = word;
    unsigned bitT  = adj[((long)b * Nn + j) * Nn + i] > 0;
    unsigned wordT = __ballot_sync(~0u, bitT);
    if (!lane) mbT[((long)b * Nn + i) * 16 + w] = wordT;
}

// ---------------- out = layernorm(tA + tB), rows of 128 ----------------
__global__ void ln_res_k(const float* __restrict__ tA, const float* __restrict__ tB,
                         float* __restrict__ out)
{
    int row = blockIdx.x, t = threadIdx.x;
    __shared__ float red[4];
    float x = tA[(long)row*128 + t] + tB[(long)row*128 + t];
    float s = x;
    for (int off = 16; off; off >>= 1) s += __shfl_xor_sync(~0u, s, off);
    if ((t & 31) == 0) red[t >> 5] = s;
    __syncthreads();
    float mean = (red[0]+red[1]+red[2]+red[3]) * (1.f/128.f);
    float d = x - mean;
    float v = d * d;
    __syncthreads();
    for (int off = 16; off; off >>= 1) v += __shfl_xor_sync(~0u, v, off);
    if ((t & 31) == 0) red[t >> 5] = v;
    __syncthreads();
    float var = (red[0]+red[1]+red[2]+red[3]) * (1.f/128.f);
    out[(long)row*128 + t] = d * rsqrtf(var + 1e-5f);
}

// ---------------- final: out[b] = mean_n concat(hf,ht) . proj_W + proj_b ----------------
__global__ void final_k(const float* __restrict__ hf, const float* __restrict__ ht,
                        const float* __restrict__ pW, const float* __restrict__ pb,
                        float* __restrict__ out)
{
    int b = blockIdx.x, t = threadIdx.x;
    const float* src = (t < 128) ? hf : ht;
    int f = t & 127;
    float w = pW[t];
    float acc = 0.f;
    for (int n = 0; n < Nn; n++) acc += src[((long)b * Nn + n) * 128 + f];
    acc *= w;
    __shared__ float red[8];
    for (int off = 16; off; off >>= 1) acc += __shfl_xor_sync(~0u, acc, off);
    if ((t & 31) == 0) red[t >> 5] = acc;
    __syncthreads();
    if (t == 0) {
        float s = 0.f;
        #pragma unroll
        for (int k = 0; k < 8; k++) s += red[k];
        out[b] = s / (float)Nn + pb[0];
    }
}

// ---------------- host orchestration ----------------
static inline BOff Z()            { return BOff{1, 0, 0}; }
static inline BOff perZ(long s)   { return BOff{1, 0, s}; }

static void attn_block(const float* in, float* out, int blk,
                       const unsigned* mb,
                       const float* att_W, const float* att_a,
                       const float* resh_W, const float* resh_b,
                       float* Wh, float* hp2, float* tmp)
{
    const float* Wblk = att_W  + (long)blk * NHEADS * 128 * 128;
    const float* ablk = att_a  + (long)blk * NHEADS * 256;
    const float* rW   = resh_W + (long)blk * 512 * 128;
    const float* rb   = resh_b + (long)blk * 128;
    const int Zc = NHEADS * Bq;   // 32

    // Wh[z] = in[b] @ W[h]     (z = h*Bq + b)
    gemm_k<0><<<dim3(2, 8, Zc), 256>>>(
        in,   BOff{Bq, (long)Nn*128, 0}, 128,
        Wblk, BOff{Bq, 0, 128*128},      128,
        nullptr, Z(),
        Wh, perZ((long)Nn*128), 128, 128);
    // hp2[b,n,h*128+o] = elu( softmax(mask, lrelu(s1 s2^T)) @ Wh )
    gatagg_k<2><<<dim3(8, Zc), 256>>>(
        Wh, ablk, mb, hp2, BOff{Bq, (long)Nn*512, 128}, 512);
    // tmp = hp2 @ resh_W + resh_b
    gemm_k<0><<<dim3(2, 64, 1), 256>>>(
        hp2, Z(), 512,
        rW,  Z(), 128,
        rb,  Z(),
        tmp, Z(), 128, 512);
    // out = LN(tmp + in)
    ln_res_k<<<MROWS, 128>>>(tmp, in, out);
}

static void out_gat(const float* in, float* dst, int widx,
                    const unsigned* mb,
                    const float* out_W, const float* out_a,
                    float* Wh)
{
    const float* Wblk = out_W + (long)widx * 128 * 128;
    const float* ablk = out_a + (long)widx * 256;
    const int Zc = Bq;

    gemm_k<0><<<dim3(2, 8, Zc), 256>>>(
        in,   perZ((long)Nn*128), 128,
        Wblk, Z(),                128,
        nullptr, Z(),
        Wh, perZ((long)Nn*128), 128, 128);
    // dst = lrelu( softmax @ Wh )
    gatagg_k<1><<<dim3(8, Zc), 256>>>(
        Wh, ablk, mb, dst, perZ((long)Nn*128), 128);
}

extern "C" void kernel_launch(void* const* d_in, const int* in_sizes, int n_in,
                              void* d_out, int out_size)
{
    const float* x      = (const float*)d_in[0];
    const int*   adj    = (const int*)  d_in[1];
    const float* f1w1 = (const float*)d_in[3];  const float* f1b1 = (const float*)d_in[4];
    const float* f1w2 = (const float*)d_in[5];  const float* f1b2 = (const float*)d_in[6];
    const float* f2w1 = (const float*)d_in[7];  const float* f2b1 = (const float*)d_in[8];
    const float* f2w2 = (const float*)d_in[9];  const float* f2b2 = (const float*)d_in[10];
    const float* f3w1 = (const float*)d_in[11]; const float* f3b1 = (const float*)d_in[12];
    const float* f3w2 = (const float*)d_in[13]; const float* f3b2 = (const float*)d_in[14];
    const float* att_W  = (const float*)d_in[15];
    const float* att_a  = (const float*)d_in[16];
    const float* resh_W = (const float*)d_in[17];
    const float* resh_b = (const float*)d_in[18];
    const float* out_W  = (const float*)d_in[19];
    const float* out_a  = (const float*)d_in[20];
    const float* proj_W = (const float*)d_in[21];
    const float* proj_b = (const float*)d_in[22];
    float* out = (float*)d_out;

    float *bufA, *bufB, *tmp, *hp2, *Wh, *hf, *ht;
    unsigned *mask, *maskT;
    cudaGetSymbolAddress((void**)&bufA, g_bufA);
    cudaGetSymbolAddress((void**)&bufB, g_bufB);
    cudaGetSymbolAddress((void**)&tmp,  g_tmp);
    cudaGetSymbolAddress((void**)&hp2,  g_hp2);
    cudaGetSymbolAddress((void**)&Wh,   g_Wh);
    cudaGetSymbolAddress((void**)&hf,   g_hf);
    cudaGetSymbolAddress((void**)&ht,   g_ht);
    cudaGetSymbolAddress((void**)&mask,  g_mask);
    cudaGetSymbolAddress((void**)&maskT, g_maskT);

    // masks
    maskbuild_k<<<dim3(Nn, Bq), 512>>>(adj, mask, maskT);

    // ---- FEL ----
    gemm_k<1><<<dim3(2, 64, 1), 256>>>(x, Z(), 32,  f1w1, Z(), 128, f1b1, Z(), bufB, Z(), 128, 32);
    gemm_k<1><<<dim3(2, 64, 1), 256>>>(bufB, Z(), 128, f1w2, Z(), 128, f1b2, Z(), bufA, Z(), 128, 128);
    gemm_k<1><<<dim3(4, 64, 1), 256>>>(bufA, Z(), 128, f2w1, Z(), 256, f2b1, Z(), tmp,  Z(), 256, 128);
    gemm_k<1><<<dim3(2, 64, 1), 256>>>(tmp,  Z(), 256, f2w2, Z(), 128, f2b2, Z(), bufB, Z(), 128, 256);
    ln_res_k<<<MROWS, 128>>>(bufB, bufA, bufA);
    gemm_k<1><<<dim3(4, 64, 1), 256>>>(bufA, Z(), 128, f3w1, Z(), 256, f3b1, Z(), tmp,  Z(), 256, 128);
    gemm_k<0><<<dim3(2, 64, 1), 256>>>(tmp,  Z(), 256, f3w2, Z(), 128, f3b2, Z(), bufB, Z(), 128, 256);
    ln_res_k<<<MROWS, 128>>>(bufB, bufA, bufA);

    // ---- forward chain (mask) ----
    for (int i = 0; i < 3; i++)
        attn_block(bufA, bufA, i, mask, att_W, att_a, resh_W, resh_b, Wh, hp2, tmp);
    out_gat(bufA, hf, 0, mask, out_W, out_a, Wh);

    // ---- transposed chain (mask_t), seeded from hf ----
    attn_block(hf,   bufB, 3, maskT, att_W, att_a, resh_W, resh_b, Wh, hp2, tmp);
    attn_block(bufB, bufB, 4, maskT, att_W, att_a, resh_W, resh_b, Wh, hp2, tmp);
    attn_block(bufB, bufB, 5, maskT, att_W, att_a, resh_W, resh_b, Wh, hp2, tmp);
    out_gat(bufB, ht, 1, maskT, out_W, out_a, Wh);

    // ---- readout ----
    final_k<<<Bq, 256>>>(hf, ht, proj_W, proj_b, out);
    (void)in_sizes; (void)n_in; (void)out_size;
}

// round 4
// speedup vs baseline: 2.1474x; 2.1474x over previous
#include <cuda_runtime.h>
#include <math.h>

#define Bq 8
#define Nn 512
#define NFEAT 32
#define NHID 128
#define NHEADS 4
#define MROWS (Bq*Nn)   // 4096

// ---------------- scratch (device globals; no allocation) ----------------
__device__ __align__(256) float g_bufA[MROWS*NHID];
__device__ __align__(256) float g_bufB[MROWS*NHID];
__device__ __align__(256) float g_tmp [MROWS*2*NHID];
__device__ __align__(256) float g_hp2 [MROWS*NHEADS*NHID];          // [b,n,H*o]
__device__ __align__(256) float g_Wh  [NHEADS*Bq*Nn*NHID];          // [z,n,o]
__device__ __align__(256) float g_att [NHEADS*Bq*Nn*Nn];            // [z,i,j]
__device__ __align__(256) float g_s1  [NHEADS*Bq*Nn];
__device__ __align__(256) float g_s2  [NHEADS*Bq*Nn];
__device__ __align__(256) float g_hf  [MROWS*NHID];
__device__ __align__(256) float g_ht  [MROWS*NHID];
__device__ __align__(256) unsigned g_mask [Bq*Nn*(Nn/32)];
__device__ __align__(256) unsigned g_maskT[Bq*Nn*(Nn/32)];

// ---------------- batched-offset descriptor ----------------
struct BOff { int mod; long inS; long outS; };
__device__ __forceinline__ long boff(BOff o, int z){
    return (long)(z % o.mod) * o.inS + (long)(z / o.mod) * o.outS;
}

// ---------------- tf32 helpers ----------------
__device__ __forceinline__ unsigned f2tf(float x){
    unsigned u; asm("cvt.rna.tf32.f32 %0, %1;" : "=r"(u) : "f"(x)); return u;
}
__device__ __forceinline__ void mma_tf32(
    float& c0, float& c1, float& c2, float& c3,
    unsigned a0, unsigned a1, unsigned a2, unsigned a3,
    unsigned b0, unsigned b1)
{
    asm volatile(
        "mma.sync.aligned.m16n8k8.row.col.f32.tf32.tf32.f32 "
        "{%0,%1,%2,%3}, {%4,%5,%6,%7}, {%8,%9}, {%0,%1,%2,%3};\n"
        : "+f"(c0), "+f"(c1), "+f"(c2), "+f"(c3)
        : "r"(a0), "r"(a1), "r"(a2), "r"(a3), "r"(b0), "r"(b1));
}

// ---------------- tensor-core GEMM: C = act(A @ W + bias), tf32 mma ----------------
// Block tile 128x128, k-tile 32, 256 threads = 8 warps (2 m x 4 n), warp tile 64x32.
// Requires M%128==0, N%128==0, K%32==0 (true for all calls here).
template<int ACT>   // 0=none 1=lrelu(0.01) 2=elu
__global__ void __launch_bounds__(256) gemm32_k(
    const float* __restrict__ A, BOff ao, int ldA,
    const float* __restrict__ W, BOff wo, int ldW,
    const float* __restrict__ bias, BOff bo,
    float* __restrict__ C, BOff co, int ldC,
    int K)
{
    int z = blockIdx.z;
    A += boff(ao, z); W += boff(wo, z); C += boff(co, z);
    if (bias) bias += boff(bo, z);

    __shared__ unsigned As[128][36];   // [m][k] tf32, pad->conflict-free frag loads
    __shared__ unsigned Bs[32][136];   // [k][n] tf32

    int tid  = threadIdx.x;
    int lane = tid & 31, warp = tid >> 5;
    int wm = (warp >> 2) * 64;         // warp row offset in tile (0 or 64)
    int wn = (warp & 3) * 32;          // warp col offset in tile (0..96)
    int g = lane >> 2, tig = lane & 3;

    int m0 = blockIdx.y * 128, n0 = blockIdx.x * 128;

    // loaders
    int arow = tid >> 3, acol = (tid & 7) * 4;    // A: 32 rows x 8 col4, x4 row-steps
    int brow = tid >> 5, bcol = (tid & 31) * 4;   // B: 8 rows x 32 col4, x4 row-steps

    float acc[4][4][4];
    #pragma unroll
    for (int mt = 0; mt < 4; mt++)
        #pragma unroll
        for (int nt = 0; nt < 4; nt++)
            #pragma unroll
            for (int c = 0; c < 4; c++) acc[mt][nt][c] = 0.f;

    for (int k0 = 0; k0 < K; k0 += 32) {
        // load + convert A tile 128x32
        #pragma unroll
        for (int q = 0; q < 4; q++) {
            int r = arow + q * 32;
            float4 v = *(const float4*)&A[(long)(m0 + r) * ldA + k0 + acol];
            unsigned u[4] = {f2tf(v.x), f2tf(v.y), f2tf(v.z), f2tf(v.w)};
            *(uint4*)&As[r][acol] = *(uint4*)u;
        }
        // load + convert B tile 32x128
        #pragma unroll
        for (int q = 0; q < 4; q++) {
            int r = brow + q * 8;
            float4 v = *(const float4*)&W[(long)(k0 + r) * ldW + n0 + bcol];
            unsigned u[4] = {f2tf(v.x), f2tf(v.y), f2tf(v.z), f2tf(v.w)};
            *(uint4*)&Bs[r][bcol] = *(uint4*)u;
        }
        __syncthreads();

        #pragma unroll
        for (int kk = 0; kk < 32; kk += 8) {
            unsigned bf[4][2];
            #pragma unroll
            for (int nt = 0; nt < 4; nt++) {
                bf[nt][0] = Bs[kk + tig][wn + nt * 8 + g];
                bf[nt][1] = Bs[kk + tig + 4][wn + nt * 8 + g];
            }
            #pragma unroll
            for (int mt = 0; mt < 4; mt++) {
                int r0 = wm + mt * 16 + g;
                unsigned a0 = As[r0][kk + tig];
                unsigned a1 = As[r0 + 8][kk + tig];
                unsigned a2 = As[r0][kk + tig + 4];
                unsigned a3 = As[r0 + 8][kk + tig + 4];
                #pragma unroll
                for (int nt = 0; nt < 4; nt++)
                    mma_tf32(acc[mt][nt][0], acc[mt][nt][1], acc[mt][nt][2], acc[mt][nt][3],
                             a0, a1, a2, a3, bf[nt][0], bf[nt][1]);
            }
        }
        __syncthreads();
    }

    // epilogue
    #pragma unroll
    for (int mt = 0; mt < 4; mt++) {
        int row0 = m0 + wm + mt * 16 + g;
        #pragma unroll
        for (int nt = 0; nt < 4; nt++) {
            int col = n0 + wn + nt * 8 + 2 * tig;
            float b0 = bias ? bias[col] : 0.f;
            float b1 = bias ? bias[col + 1] : 0.f;
            float v[4] = {acc[mt][nt][0] + b0, acc[mt][nt][1] + b1,
                          acc[mt][nt][2] + b0, acc[mt][nt][3] + b1};
            #pragma unroll
            for (int c = 0; c < 4; c++) {
                if (ACT == 1) v[c] = v[c] > 0.f ? v[c] : 0.01f * v[c];
                else if (ACT == 2) v[c] = v[c] > 0.f ? v[c] : (expf(v[c]) - 1.f);
            }
            *(float2*)&C[(long)row0 * ldC + col]       = make_float2(v[0], v[1]);
            *(float2*)&C[(long)(row0 + 8) * ldC + col] = make_float2(v[2], v[3]);
        }
    }
}

// ---------------- adjacency -> packed bitmask (normal + transposed) ----------------
__global__ void maskbuild_k(const int* __restrict__ adj,
                            unsigned* __restrict__ mb, unsigned* __restrict__ mbT)
{
    int i = blockIdx.x, b = blockIdx.y, j = threadIdx.x;
    int lane = j & 31, w = j >> 5;
    unsigned bit  = adj[((long)b * Nn + i) * Nn + j] > 0;
    unsigned word = __ballot_sync(~0u, bit);
    if (!lane) mb[((long)b * Nn + i) * 16 + w] = word;
    unsigned bitT  = adj[((long)b * Nn + j) * Nn + i] > 0;
    unsigned wordT = __ballot_sync(~0u, bitT);
    if (!lane) mbT[((long)b * Nn + i) * 16 + w] = wordT;
}

// ---------------- s1/s2 = Wh . a[:o], Wh . a[o:] (one warp per row) ----------------
__global__ void s1s2_k(const float* __restrict__ Wh, const float* __restrict__ a_base,
                       float* __restrict__ s1, float* __restrict__ s2, int nrows)
{
    int warp = (blockIdx.x * blockDim.x + threadIdx.x) >> 5;
    int lane = threadIdx.x & 31;
    if (warp >= nrows) return;
    int z = warp / Nn;
    int h = z / Bq;
    const float* a = a_base + h * 256;
    const float* w = Wh + (long)warp * NHID;
    float4 wv = *(const float4*)&w[lane * 4];
    float4 a1 = *(const float4*)&a[lane * 4];
    float4 a2 = *(const float4*)&a[128 + lane * 4];
    float d1 = wv.x*a1.x + wv.y*a1.y + wv.z*a1.z + wv.w*a1.w;
    float d2 = wv.x*a2.x + wv.y*a2.y + wv.z*a2.z + wv.w*a2.w;
    for (int off = 16; off; off >>= 1) {
        d1 += __shfl_xor_sync(~0u, d1, off);
        d2 += __shfl_xor_sync(~0u, d2, off);
    }
    if (!lane) { s1[warp] = d1; s2[warp] = d2; }
}

// ---------------- masked softmax over rank-1 leaky scores ----------------
__global__ void softmax_k(const float* __restrict__ s1, const float* __restrict__ s2,
                          const unsigned* __restrict__ maskbits, float* __restrict__ att)
{
    int i = blockIdx.x, z = blockIdx.y, t = threadIdx.x;   // 128 threads
    int b = z % Bq;
    __shared__ float s2s[Nn];
    __shared__ unsigned mw[16];
    __shared__ float red[4];
    const float* s2z = s2 + (long)z * Nn;
    #pragma unroll
    for (int k = 0; k < 4; k++) s2s[t + k*128] = s2z[t + k*128];
    if (t < 16) mw[t] = maskbits[((long)b * Nn + i) * 16 + t];
    __syncthreads();

    float s1i = s1[(long)z * Nn + i];
    float e[4]; bool valid[4];
    float m = -1e30f;
    #pragma unroll
    for (int k = 0; k < 4; k++) {
        int j = t + k * 128;
        float v = s1i * s2s[j];
        v = v > 0.f ? v : 0.01f * v;
        bool ok = (mw[j >> 5] >> (j & 31)) & 1;
        e[k] = v; valid[k] = ok;
        if (ok && v > m) m = v;
    }
    for (int off = 16; off; off >>= 1) m = fmaxf(m, __shfl_xor_sync(~0u, m, off));
    if ((t & 31) == 0) red[t >> 5] = m;
    __syncthreads();
    m = fmaxf(fmaxf(red[0], red[1]), fmaxf(red[2], red[3]));

    float p[4]; float s = 0.f;
    #pragma unroll
    for (int k = 0; k < 4; k++) { p[k] = valid[k] ? expf(e[k] - m) : 0.f; s += p[k]; }
    for (int off = 16; off; off >>= 1) s += __shfl_xor_sync(~0u, s, off);
    __syncthreads();
    if ((t & 31) == 0) red[t >> 5] = s;
    __syncthreads();
    s = red[0] + red[1] + red[2] + red[3];
    float inv = s > 0.f ? 1.f / s : 0.f;

    float* arow = att + ((long)z * Nn + i) * Nn;
    #pragma unroll
    for (int k = 0; k < 4; k++) arow[t + k*128] = p[k] * inv;
}

// ---------------- out = layernorm(tA + tB), rows of 128 ----------------
__global__ void ln_res_k(const float* __restrict__ tA, const float* __restrict__ tB,
                         float* __restrict__ out)
{
    int row = blockIdx.x, t = threadIdx.x;
    __shared__ float red[4];
    float x = tA[(long)row*128 + t] + tB[(long)row*128 + t];
    float s = x;
    for (int off = 16; off; off >>= 1) s += __shfl_xor_sync(~0u, s, off);
    if ((t & 31) == 0) red[t >> 5] = s;
    __syncthreads();
    float mean = (red[0]+red[1]+red[2]+red[3]) * (1.f/128.f);
    float d = x - mean;
    float v = d * d;
    __syncthreads();
    for (int off = 16; off; off >>= 1) v += __shfl_xor_sync(~0u, v, off);
    if ((t & 31) == 0) red[t >> 5] = v;
    __syncthreads();
    float var = (red[0]+red[1]+red[2]+red[3]) * (1.f/128.f);
    out[(long)row*128 + t] = d * rsqrtf(var + 1e-5f);
}

// ---------------- final: out[b] = mean_n concat(hf,ht) . proj_W + proj_b ----------------
__global__ void final_k(const float* __restrict__ hf, const float* __restrict__ ht,
                        const float* __restrict__ pW, const float* __restrict__ pb,
                        float* __restrict__ out)
{
    int b = blockIdx.x, t = threadIdx.x;
    const float* src = (t < 128) ? hf : ht;
    int f = t & 127;
    float w = pW[t];
    float acc = 0.f;
    for (int n = 0; n < Nn; n++) acc += src[((long)b * Nn + n) * 128 + f];
    acc *= w;
    __shared__ float red[8];
    for (int off = 16; off; off >>= 1) acc += __shfl_xor_sync(~0u, acc, off);
    if ((t & 31) == 0) red[t >> 5] = acc;
    __syncthreads();
    if (t == 0) {
        float s = 0.f;
        #pragma unroll
        for (int k = 0; k < 8; k++) s += red[k];
        out[b] = s / (float)Nn + pb[0];
    }
}

// ---------------- host orchestration ----------------
static inline BOff Z()            { return BOff{1, 0, 0}; }
static inline BOff perZ(long s)   { return BOff{1, 0, s}; }

static void attn_block(const float* in, float* out, int blk,
                       const unsigned* mb,
                       const float* att_W, const float* att_a,
                       const float* resh_W, const float* resh_b,
                       float* Wh, float* att, float* hp2, float* tmp,
                       float* s1, float* s2)
{
    const float* Wblk = att_W  + (long)blk * NHEADS * 128 * 128;
    const float* ablk = att_a  + (long)blk * NHEADS * 256;
    const float* rW   = resh_W + (long)blk * 512 * 128;
    const float* rb   = resh_b + (long)blk * 128;
    const int Zc = NHEADS * Bq;   // 32

    // Wh[z] = in[b] @ W[h]     (z = h*Bq + b)
    gemm32_k<0><<<dim3(1, 4, Zc), 256>>>(
        in,   BOff{Bq, (long)Nn*128, 0}, 128,
        Wblk, BOff{Bq, 0, 128*128},      128,
        nullptr, Z(),
        Wh, perZ((long)Nn*128), 128, 128);
    s1s2_k<<<(Zc*Nn)/8, 256>>>(Wh, ablk, s1, s2, Zc*Nn);
    softmax_k<<<dim3(Nn, Zc), 128>>>(s1, s2, mb, att);
    // hp2[b,n,h*128+o] = elu( att[z] @ Wh[z] )
    gemm32_k<2><<<dim3(1, 4, Zc), 256>>>(
        att, perZ((long)Nn*Nn), Nn,
        Wh,  perZ((long)Nn*128), 128,
        nullptr, Z(),
        hp2, BOff{Bq, (long)Nn*512, 128}, 512, Nn);
    // tmp = hp2 @ resh_W + resh_b
    gemm32_k<0><<<dim3(1, 32, 1), 256>>>(
        hp2, Z(), 512,
        rW,  Z(), 128,
        rb,  Z(),
        tmp, Z(), 128, 512);
    // out = LN(tmp + in)
    ln_res_k<<<MROWS, 128>>>(tmp, in, out);
}

static void out_gat(const float* in, float* dst, int widx,
                    const unsigned* mb,
                    const float* out_W, const float* out_a,
                    float* Wh, float* att, float* s1, float* s2)
{
    const float* Wblk = out_W + (long)widx * 128 * 128;
    const float* ablk = out_a + (long)widx * 256;
    const int Zc = Bq;

    gemm32_k<0><<<dim3(1, 4, Zc), 256>>>(
        in,   perZ((long)Nn*128), 128,
        Wblk, Z(),                128,
        nullptr, Z(),
        Wh, perZ((long)Nn*128), 128, 128);
    s1s2_k<<<(Zc*Nn)/8, 256>>>(Wh, ablk, s1, s2, Zc*Nn);
    softmax_k<<<dim3(Nn, Zc), 128>>>(s1, s2, mb, att);
    // dst = lrelu( att @ Wh )
    gemm32_k<1><<<dim3(1, 4, Zc), 256>>>(
        att, perZ((long)Nn*Nn), Nn,
        Wh,  perZ((long)Nn*128), 128,
        nullptr, Z(),
        dst, perZ((long)Nn*128), 128, Nn);
}

extern "C" void kernel_launch(void* const* d_in, const int* in_sizes, int n_in,
                              void* d_out, int out_size)
{
    const float* x      = (const float*)d_in[0];
    const int*   adj    = (const int*)  d_in[1];
    const float* f1w1 = (const float*)d_in[3];  const float* f1b1 = (const float*)d_in[4];
    const float* f1w2 = (const float*)d_in[5];  const float* f1b2 = (const float*)d_in[6];
    const float* f2w1 = (const float*)d_in[7];  const float* f2b1 = (const float*)d_in[8];
    const float* f2w2 = (const float*)d_in[9];  const float* f2b2 = (const float*)d_in[10];
    const float* f3w1 = (const float*)d_in[11]; const float* f3b1 = (const float*)d_in[12];
    const float* f3w2 = (const float*)d_in[13]; const float* f3b2 = (const float*)d_in[14];
    const float* att_W  = (const float*)d_in[15];
    const float* att_a  = (const float*)d_in[16];
    const float* resh_W = (const float*)d_in[17];
    const float* resh_b = (const float*)d_in[18];
    const float* out_W  = (const float*)d_in[19];
    const float* out_a  = (const float*)d_in[20];
    const float* proj_W = (const float*)d_in[21];
    const float* proj_b = (const float*)d_in[22];
    float* out = (float*)d_out;

    float *bufA, *bufB, *tmp, *hp2, *Wh, *att, *s1, *s2, *hf, *ht;
    unsigned *mask, *maskT;
    cudaGetSymbolAddress((void**)&bufA, g_bufA);
    cudaGetSymbolAddress((void**)&bufB, g_bufB);
    cudaGetSymbolAddress((void**)&tmp,  g_tmp);
    cudaGetSymbolAddress((void**)&hp2,  g_hp2);
    cudaGetSymbolAddress((void**)&Wh,   g_Wh);
    cudaGetSymbolAddress((void**)&att,  g_att);
    cudaGetSymbolAddress((void**)&s1,   g_s1);
    cudaGetSymbolAddress((void**)&s2,   g_s2);
    cudaGetSymbolAddress((void**)&hf,   g_hf);
    cudaGetSymbolAddress((void**)&ht,   g_ht);
    cudaGetSymbolAddress((void**)&mask,  g_mask);
    cudaGetSymbolAddress((void**)&maskT, g_maskT);

    // masks
    maskbuild_k<<<dim3(Nn, Bq), 512>>>(adj, mask, maskT);

    // ---- FEL ----
    gemm32_k<1><<<dim3(1, 32, 1), 256>>>(x, Z(), 32,  f1w1, Z(), 128, f1b1, Z(), bufB, Z(), 128, 32);
    gemm32_k<1><<<dim3(1, 32, 1), 256>>>(bufB, Z(), 128, f1w2, Z(), 128, f1b2, Z(), bufA, Z(), 128, 128);
    gemm32_k<1><<<dim3(2, 32, 1), 256>>>(bufA, Z(), 128, f2w1, Z(), 256, f2b1, Z(), tmp,  Z(), 256, 128);
    gemm32_k<1><<<dim3(1, 32, 1), 256>>>(tmp,  Z(), 256, f2w2, Z(), 128, f2b2, Z(), bufB, Z(), 128, 256);
    ln_res_k<<<MROWS, 128>>>(bufB, bufA, bufA);
    gemm32_k<1><<<dim3(2, 32, 1), 256>>>(bufA, Z(), 128, f3w1, Z(), 256, f3b1, Z(), tmp,  Z(), 256, 128);
    gemm32_k<0><<<dim3(1, 32, 1), 256>>>(tmp,  Z(), 256, f3w2, Z(), 128, f3b2, Z(), bufB, Z(), 128, 256);
    ln_res_k<<<MROWS, 128>>>(bufB, bufA, bufA);

    // ---- forward chain (mask) ----
    for (int i = 0; i < 3; i++)
        attn_block(bufA, bufA, i, mask, att_W, att_a, resh_W, resh_b, Wh, att, hp2, tmp, s1, s2);
    out_gat(bufA, hf, 0, mask, out_W, out_a, Wh, att, s1, s2);

    // ---- transposed chain (mask_t), seeded from hf ----
    attn_block(hf,   bufB, 3, maskT, att_W, att_a, resh_W, resh_b, Wh, att, hp2, tmp, s1, s2);
    attn_block(bufB, bufB, 4, maskT, att_W, att_a, resh_W, resh_b, Wh, att, hp2, tmp, s1, s2);
    attn_block(bufB, bufB, 5, maskT, att_W, att_a, resh_W, resh_b, Wh, att, hp2, tmp, s1, s2);
    out_gat(bufB, ht, 1, maskT, out_W, out_a, Wh, att, s1, s2);

    // ---- readout ----
    final_k<<<Bq, 256>>>(hf, ht, proj_W, proj_b, out);
    (void)in_sizes; (void)n_in; (void)out_size;
}

// round 7
// speedup vs baseline: 2.2475x; 1.0466x over previous
#include <cuda_runtime.h>
#include <math.h>

#define Bq 8
#define Nn 512
#define NFEAT 32
#define NHID 128
#define NHEADS 4
#define MROWS (Bq*Nn)   // 4096

// ---------------- scratch (device globals; no allocation) ----------------
__device__ __align__(256) float g_bufA[MROWS*NHID];
__device__ __align__(256) float g_bufB[MROWS*NHID];
__device__ __align__(256) float g_tmp [MROWS*2*NHID];
__device__ __align__(256) float g_hp2 [MROWS*NHEADS*NHID];          // [b,n,H*o]
__device__ __align__(256) float g_Wh  [NHEADS*Bq*Nn*NHID];          // [z,n,o]
__device__ __align__(256) float g_s1  [NHEADS*Bq*Nn];
__device__ __align__(256) float g_s2  [NHEADS*Bq*Nn];
__device__ __align__(256) float g_mI  [NHEADS*Bq*Nn];
__device__ __align__(256) float g_zI  [NHEADS*Bq*Nn];
__device__ __align__(256) float g_hf  [MROWS*NHID];
__device__ __align__(256) float g_ht  [MROWS*NHID];
__device__ __align__(256) unsigned g_mask [Bq*Nn*(Nn/32)];
__device__ __align__(256) unsigned g_maskT[Bq*Nn*(Nn/32)];

// ---------------- batched-offset descriptor ----------------
struct BOff { int mod; long inS; long outS; };
__device__ __forceinline__ long boff(BOff o, int z){
    return (long)(z % o.mod) * o.inS + (long)(z / o.mod) * o.outS;
}

// ---------------- tf32 helpers ----------------
__device__ __forceinline__ unsigned f2tf(float x){
    unsigned u; asm("cvt.rna.tf32.f32 %0, %1;" : "=r"(u) : "f"(x)); return u;
}
__device__ __forceinline__ void mma_tf32(
    float& c0, float& c1, float& c2, float& c3,
    unsigned a0, unsigned a1, unsigned a2, unsigned a3,
    unsigned b0, unsigned b1)
{
    asm volatile(
        "mma.sync.aligned.m16n8k8.row.col.f32.tf32.tf32.f32 "
        "{%0,%1,%2,%3}, {%4,%5,%6,%7}, {%8,%9}, {%0,%1,%2,%3};\n"
        : "+f"(c0), "+f"(c1), "+f"(c2), "+f"(c3)
        : "r"(a0), "r"(a1), "r"(a2), "r"(a3), "r"(b0), "r"(b1));
}

// ============================================================================
// Pipelined tf32 GEMM: C = act(A @ W + bias).  Block tile MT x 128, k-tile 32.
// 256 thr = 8 warps (2m x 4n); warp tile (MT/2) x 32. Double-buffered smem,
// register prefetch, one sync per k-tile.
// FUSE: additionally computes s1[i]=Wh[i,:]·a[:128], s2[i]=Wh[i,:]·a[128:]
// (requires gridDim.x==1, N==128).
// ============================================================================
template<int MT, int ACT, bool FUSE>   // ACT: 0=none 1=lrelu
__global__ void __launch_bounds__(256) gemm32_k(
    const float* __restrict__ A, BOff ao, int ldA,
    const float* __restrict__ W, BOff wo, int ldW,
    const float* __restrict__ bias, BOff bo,
    float* __restrict__ C, BOff co, int ldC, int K,
    float* __restrict__ s1g, float* __restrict__ s2g,
    const float* __restrict__ a_base)
{
    constexpr int MTW = MT / 32;       // mt count and A-load passes
    extern __shared__ unsigned dsm[];
    unsigned (*As)[MT][36]  = (unsigned(*)[MT][36])dsm;            // [2][MT][36]
    unsigned (*Bs)[32][136] = (unsigned(*)[32][136])(dsm + 2*MT*36);
    __shared__ float s1p[MT], s2p[MT];

    int z = blockIdx.z;
    A += boff(ao, z); W += boff(wo, z); C += boff(co, z);
    if (bias) bias += boff(bo, z);

    int tid  = threadIdx.x;
    int lane = tid & 31, warp = tid >> 5;
    int wm = (warp >> 2) * (MT/2);
    int wn = (warp & 3) * 32;
    int g = lane >> 2, tig = lane & 3;
    int m0 = blockIdx.y * MT, n0 = blockIdx.x * 128;

    int arow = tid >> 3, acol = (tid & 7) * 4;    // A: 32 rows/pass
    int brow = tid >> 5, bcol = (tid & 31) * 4;   // B: 8 rows/pass, 4 passes

    if (FUSE && tid < MT) { s1p[tid] = 0.f; s2p[tid] = 0.f; }

    float4 aR[MTW], bR[4];
    #pragma unroll
    for (int q = 0; q < MTW; q++)
        aR[q] = *(const float4*)&A[(long)(m0 + arow + q*32) * ldA + acol];
    #pragma unroll
    for (int q = 0; q < 4; q++)
        bR[q] = *(const float4*)&W[(long)(brow + q*8) * ldW + n0 + bcol];
    #pragma unroll
    for (int q = 0; q < MTW; q++) {
        unsigned u[4] = {f2tf(aR[q].x), f2tf(aR[q].y), f2tf(aR[q].z), f2tf(aR[q].w)};
        *(uint4*)&As[0][arow + q*32][acol] = *(uint4*)u;
    }
    #pragma unroll
    for (int q = 0; q < 4; q++) {
        unsigned u[4] = {f2tf(bR[q].x), f2tf(bR[q].y), f2tf(bR[q].z), f2tf(bR[q].w)};
        *(uint4*)&Bs[0][brow + q*8][bcol] = *(uint4*)u;
    }
    __syncthreads();

    float acc[MTW][4][4];
    #pragma unroll
    for (int mt = 0; mt < MTW; mt++)
        #pragma unroll
        for (int nt = 0; nt < 4; nt++)
            #pragma unroll
            for (int c = 0; c < 4; c++) acc[mt][nt][c] = 0.f;

    int nIter = K / 32;
    for (int it = 0; it < nIter; it++) {
        int cur = it & 1, nxt = cur ^ 1;
        if (it + 1 < nIter) {
            int k0 = (it + 1) * 32;
            #pragma unroll
            for (int q = 0; q < MTW; q++)
                aR[q] = *(const float4*)&A[(long)(m0 + arow + q*32) * ldA + k0 + acol];
            #pragma unroll
            for (int q = 0; q < 4; q++)
                bR[q] = *(const float4*)&W[(long)(k0 + brow + q*8) * ldW + n0 + bcol];
        }
        #pragma unroll
        for (int kk = 0; kk < 32; kk += 8) {
            unsigned bf[4][2];
            #pragma unroll
            for (int nt = 0; nt < 4; nt++) {
                bf[nt][0] = Bs[cur][kk + tig][wn + nt*8 + g];
                bf[nt][1] = Bs[cur][kk + tig + 4][wn + nt*8 + g];
            }
            #pragma unroll
            for (int mt = 0; mt < MTW; mt++) {
                int r0 = wm + mt*16 + g;
                unsigned a0 = As[cur][r0][kk + tig];
                unsigned a1 = As[cur][r0 + 8][kk + tig];
                unsigned a2 = As[cur][r0][kk + tig + 4];
                unsigned a3 = As[cur][r0 + 8][kk + tig + 4];
                #pragma unroll
                for (int nt = 0; nt < 4; nt++)
                    mma_tf32(acc[mt][nt][0], acc[mt][nt][1], acc[mt][nt][2], acc[mt][nt][3],
                             a0, a1, a2, a3, bf[nt][0], bf[nt][1]);
            }
        }
        if (it + 1 < nIter) {
            #pragma unroll
            for (int q = 0; q < MTW; q++) {
                unsigned u[4] = {f2tf(aR[q].x), f2tf(aR[q].y), f2tf(aR[q].z), f2tf(aR[q].w)};
                *(uint4*)&As[nxt][arow + q*32][acol] = *(uint4*)u;
            }
            #pragma unroll
            for (int q = 0; q < 4; q++) {
                unsigned u[4] = {f2tf(bR[q].x), f2tf(bR[q].y), f2tf(bR[q].z), f2tf(bR[q].w)};
                *(uint4*)&Bs[nxt][brow + q*8][bcol] = *(uint4*)u;
            }
        }
        __syncthreads();
    }

    // epilogue: bias + act + store
    #pragma unroll
    for (int mt = 0; mt < MTW; mt++) {
        int row0 = m0 + wm + mt*16 + g;
        #pragma unroll
        for (int nt = 0; nt < 4; nt++) {
            int col = n0 + wn + nt*8 + 2*tig;
            float b0 = bias ? bias[col] : 0.f;
            float b1 = bias ? bias[col + 1] : 0.f;
            float v[4] = {acc[mt][nt][0] + b0, acc[mt][nt][1] + b1,
                          acc[mt][nt][2] + b0, acc[mt][nt][3] + b1};
            #pragma unroll
            for (int c = 0; c < 4; c++)
                if (ACT == 1) v[c] = v[c] > 0.f ? v[c] : 0.01f * v[c];
            *(float2*)&C[(long)row0 * ldC + col]       = make_float2(v[0], v[1]);
            *(float2*)&C[(long)(row0 + 8) * ldC + col] = make_float2(v[2], v[3]);
        }
    }

    if (FUSE) {
        const float* av = a_base + (z / Bq) * 256;
        #pragma unroll
        for (int mt = 0; mt < MTW; mt++) {
            int rl = wm + mt*16 + g;
            float p1a = 0.f, p2a = 0.f, p1b = 0.f, p2b = 0.f;
            #pragma unroll
            for (int nt = 0; nt < 4; nt++) {
                int col = wn + nt*8 + 2*tig;
                float a10 = av[col], a11 = av[col+1];
                float a20 = av[128+col], a21 = av[128+col+1];
                p1a += acc[mt][nt][0]*a10 + acc[mt][nt][1]*a11;
                p2a += acc[mt][nt][0]*a20 + acc[mt][nt][1]*a21;
                p1b += acc[mt][nt][2]*a10 + acc[mt][nt][3]*a11;
                p2b += acc[mt][nt][2]*a20 + acc[mt][nt][3]*a21;
            }
            atomicAdd(&s1p[rl], p1a);     atomicAdd(&s2p[rl], p2a);
            atomicAdd(&s1p[rl + 8], p1b); atomicAdd(&s2p[rl + 8], p2b);
        }
        __syncthreads();
        if (tid < MT) {
            long row = (long)z * Nn + m0 + tid;
            s1g[row] = s1p[tid];
            s2g[row] = s2p[tid];
        }
    }
}

// ============================================================================
// rowstat: per (z,i) masked softmax max + inverse denominator
// ============================================================================
__global__ void rowstat_k(const float* __restrict__ s1, const float* __restrict__ s2,
                          const unsigned* __restrict__ maskbits,
                          float* __restrict__ mI, float* __restrict__ zI)
{
    int row = blockIdx.x * 8 + (threadIdx.x >> 5);
    int lane = threadIdx.x & 31;
    int z = row >> 9, i = row & 511, b = z & 7;
    const float* s2z = s2 + (long)z * Nn;
    const unsigned* mrow = maskbits + ((long)b * Nn + i) * 16;
    float s1i = s1[row];

    float v[16];
    float m = -1e30f;
    #pragma unroll
    for (int k = 0; k < 16; k++) {
        unsigned w = mrow[k];
        float t = s1i * s2z[k*32 + lane];
        t = t > 0.f ? t : 0.01f * t;
        bool ok = (w >> lane) & 1;
        v[k] = ok ? t : -1e30f;
        if (ok && t > m) m = t;
    }
    #pragma unroll
    for (int off = 16; off; off >>= 1) m = fmaxf(m, __shfl_xor_sync(~0u, m, off));
    if (m < -1e29f) m = 0.f;
    float s = 0.f;
    #pragma unroll
    for (int k = 0; k < 16; k++)
        if (v[k] > -1e29f) s += __expf(v[k] - m);
    #pragma unroll
    for (int off = 16; off; off >>= 1) s += __shfl_xor_sync(~0u, s, off);
    if (!lane) { mI[row] = m; zI[row] = s > 0.f ? 1.f / s : 0.f; }
}

// ============================================================================
// Fused att-GEMM: out = act( P @ Wh ), P generated on the fly:
// P[i,j] = mask ? exp(lrelu(s1_i s2_j) - m_i) * zinv_i : 0
// Block tile 128 x 128, k-tile 32 over j. 256 thr, same MMA layout (MT=128).
// ============================================================================
template<int ACT>   // 1=lrelu 2=elu
__global__ void __launch_bounds__(256) attgemm_k(
    const float* __restrict__ Wh,
    const float* __restrict__ s1, const float* __restrict__ s2,
    const float* __restrict__ mI, const float* __restrict__ zI,
    const unsigned* __restrict__ maskbits,
    float* __restrict__ out, BOff co, int ldC)
{
    extern __shared__ unsigned dsm[];
    unsigned (*As)[128][36]  = (unsigned(*)[128][36])dsm;            // 2*128*36
    unsigned (*Bs)[32][136]  = (unsigned(*)[32][136])(dsm + 2*128*36);
    float*    s2s = (float*)(dsm + 2*128*36 + 2*32*136);             // [512]
    float*    s1s = s2s + 512;                                        // [128]
    float*    mIs = s1s + 128;                                        // [128]
    float*    zIs = mIs + 128;                                        // [128]
    unsigned* mw  = (unsigned*)(zIs + 128);                           // [128*16]

    int z = blockIdx.y, b = z & 7;
    const float* whz = Wh + (long)z * Nn * NHID;
    float* outz = out + boff(co, z);
    int i0 = blockIdx.x * 128;

    int tid  = threadIdx.x;
    int lane = tid & 31, warp = tid >> 5;
    int wm = (warp >> 2) * 64, wn = (warp & 3) * 32;
    int g = lane >> 2, tig = lane & 3;
    int brow = tid >> 5, bcol = (tid & 31) * 4;

    // stage row data
    for (int t = tid; t < Nn; t += 256) s2s[t] = s2[(long)z * Nn + t];
    if (tid < 128) {
        long r = (long)z * Nn + i0 + tid;
        s1s[tid] = s1[r]; mIs[tid] = mI[r]; zIs[tid] = zI[r];
    }
    for (int t = tid; t < 128*16; t += 256)
        mw[t] = maskbits[((long)b * Nn + i0 + (t >> 4)) * 16 + (t & 15)];
    __syncthreads();

    // att tile generator
    int gi = tid >> 1, gh = tid & 1;
    float gs1 = s1s[gi], gmi = mIs[gi], gzi = zIs[gi];
    const unsigned* gmw = &mw[gi * 16];

    // prologue: generate As[0], load+store Bs[0]
    {
        unsigned word = gmw[0];
        #pragma unroll
        for (int u = 0; u < 16; u++) {
            int j = gh*16 + u;
            float v = gs1 * s2s[j];
            v = v > 0.f ? v : 0.01f * v;
            float p = ((word >> j) & 1) ? __expf(v - gmi) * gzi : 0.f;
            As[0][gi][j] = f2tf(p);
        }
        float4 bR[4];
        #pragma unroll
        for (int q = 0; q < 4; q++)
            bR[q] = *(const float4*)&whz[(long)(brow + q*8) * NHID + bcol];
        #pragma unroll
        for (int q = 0; q < 4; q++) {
            unsigned u[4] = {f2tf(bR[q].x), f2tf(bR[q].y), f2tf(bR[q].z), f2tf(bR[q].w)};
            *(uint4*)&Bs[0][brow + q*8][bcol] = *(uint4*)u;
        }
    }
    __syncthreads();

    float acc[4][4][4];
    #pragma unroll
    for (int mt = 0; mt < 4; mt++)
        #pragma unroll
        for (int nt = 0; nt < 4; nt++)
            #pragma unroll
            for (int c = 0; c < 4; c++) acc[mt][nt][c] = 0.f;

    const int nIter = Nn / 32;   // 16
    for (int it = 0; it < nIter; it++) {
        int cur = it & 1, nxt = cur ^ 1;
        float4 bR[4];
        if (it + 1 < nIter) {
            int j0 = (it + 1) * 32;
            #pragma unroll
            for (int q = 0; q < 4; q++)
                bR[q] = *(const float4*)&whz[(long)(j0 + brow + q*8) * NHID + bcol];
        }
        #pragma unroll
        for (int kk = 0; kk < 32; kk += 8) {
            unsigned bf[4][2];
            #pragma unroll
            for (int nt = 0; nt < 4; nt++) {
                bf[nt][0] = Bs[cur][kk + tig][wn + nt*8 + g];
                bf[nt][1] = Bs[cur][kk + tig + 4][wn + nt*8 + g];
            }
            #pragma unroll
            for (int mt = 0; mt < 4; mt++) {
                int r0 = wm + mt*16 + g;
                unsigned a0 = As[cur][r0][kk + tig];
                unsigned a1 = As[cur][r0 + 8][kk + tig];
                unsigned a2 = As[cur][r0][kk + tig + 4];
                unsigned a3 = As[cur][r0 + 8][kk + tig + 4];
                #pragma unroll
                for (int nt = 0; nt < 4; nt++)
                    mma_tf32(acc[mt][nt][0], acc[mt][nt][1], acc[mt][nt][2], acc[mt][nt][3],
                             a0, a1, a2, a3, bf[nt][0], bf[nt][1]);
            }
        }
        if (it + 1 < nIter) {
            int j0 = (it + 1) * 32;
            unsigned word = gmw[j0 >> 5];
            #pragma unroll
            for (int u = 0; u < 16; u++) {
                int jj = gh*16 + u;
                float v = gs1 * s2s[j0 + jj];
                v = v > 0.f ? v : 0.01f * v;
                float p = ((word >> jj) & 1) ? __expf(v - gmi) * gzi : 0.f;
                As[nxt][gi][jj] = f2tf(p);
            }
            #pragma unroll
            for (int q = 0; q < 4; q++) {
                unsigned u[4] = {f2tf(bR[q].x), f2tf(bR[q].y), f2tf(bR[q].z), f2tf(bR[q].w)};
                *(uint4*)&Bs[nxt][brow + q*8][bcol] = *(uint4*)u;
            }
        }
        __syncthreads();
    }

    #pragma unroll
    for (int mt = 0; mt < 4; mt++) {
        int row0 = i0 + wm + mt*16 + g;
        #pragma unroll
        for (int nt = 0; nt < 4; nt++) {
            int col = wn + nt*8 + 2*tig;
            float v[4] = {acc[mt][nt][0], acc[mt][nt][1], acc[mt][nt][2], acc[mt][nt][3]};
            #pragma unroll
            for (int c = 0; c < 4; c++) {
                if (ACT == 1) v[c] = v[c] > 0.f ? v[c] : 0.01f * v[c];
                else if (ACT == 2) v[c] = v[c] > 0.f ? v[c] : (expf(v[c]) - 1.f);
            }
            *(float2*)&outz[(long)row0 * ldC + col]       = make_float2(v[0], v[1]);
            *(float2*)&outz[(long)(row0 + 8) * ldC + col] = make_float2(v[2], v[3]);
        }
    }
}

// ---------------- adjacency -> packed bitmask (normal + transposed) ----------------
__global__ void maskbuild_k(const int* __restrict__ adj,
                            unsigned* __restrict__ mb, unsigned* __restrict__ mbT)
{
    int i = blockIdx.x, b = blockIdx.y, j = threadIdx.x;
    int lane = j & 31, w = j >> 5;
    unsigned bit  = adj[((long)b * Nn + i) * Nn + j] > 0;
    unsigned word = __ballot_sync(~0u, bit);
    if (!lane) mb[((long)b * Nn + i) * 16 + w] = word;
    unsigned bitT  = adj[((long)b * Nn + j) * Nn + i] > 0;
    unsigned wordT = __ballot_sync(~0u, bitT);
    if (!lane) mbT[((long)b * Nn + i) * 16 + w] = wordT;
}

// ---------------- out = layernorm(tA + tB), rows of 128 ----------------
__global__ void ln_res_k(const float* __restrict__ tA, const float* __restrict__ tB,
                         float* __restrict__ out)
{
    int row = blockIdx.x, t = threadIdx.x;
    __shared__ float red[4];
    float x = tA[(long)row*128 + t] + tB[(long)row*128 + t];
    float s = x;
    for (int off = 16; off; off >>= 1) s += __shfl_xor_sync(~0u, s, off);
    if ((t & 31) == 0) red[t >> 5] = s;
    __syncthreads();
    float mean = (red[0]+red[1]+red[2]+red[3]) * (1.f/128.f);
    float d = x - mean;
    float v = d * d;
    __syncthreads();
    for (int off = 16; off; off >>= 1) v += __shfl_xor_sync(~0u, v, off);
    if ((t & 31) == 0) red[t >> 5] = v;
    __syncthreads();
    float var = (red[0]+red[1]+red[2]+red[3]) * (1.f/128.f);
    out[(long)row*128 + t] = d * rsqrtf(var + 1e-5f);
}

// ---------------- final: out[b] = mean_n concat(hf,ht) . proj_W + proj_b ----------------
__global__ void final_k(const float* __restrict__ hf, const float* __restrict__ ht,
                        const float* __restrict__ pW, const float* __restrict__ pb,
                        float* __restrict__ out)
{
    int b = blockIdx.x, t = threadIdx.x;
    const float* src = (t < 128) ? hf : ht;
    int f = t & 127;
    float w = pW[t];
    float acc = 0.f;
    for (int n = 0; n < Nn; n++) acc += src[((long)b * Nn + n) * 128 + f];
    acc *= w;
    __shared__ float red[8];
    for (int off = 16; off; off >>= 1) acc += __shfl_xor_sync(~0u, acc, off);
    if ((t & 31) == 0) red[t >> 5] = acc;
    __syncthreads();
    if (t == 0) {
        float s = 0.f;
        #pragma unroll
        for (int k = 0; k < 8; k++) s += red[k];
        out[b] = s / (float)Nn + pb[0];
    }
}

// ---------------- host orchestration ----------------
static inline BOff Z()            { return BOff{1, 0, 0}; }
static inline BOff perZ(long s)   { return BOff{1, 0, s}; }

#define SMEM64  ((2*64*36 + 2*32*136) * 4)                    // 53248
#define SMEMATT ((2*128*36 + 2*32*136 + 512+128+128+128) * 4 + 128*16*4)   // 83456

static void attn_block(const float* in, float* out, int blk,
                       const unsigned* mb,
                       const float* att_W, const float* att_a,
                       const float* resh_W, const float* resh_b,
                       float* Wh, float* hp2, float* tmp,
                       float* s1, float* s2, float* mI, float* zI)
{
    const float* Wblk = att_W  + (long)blk * NHEADS * 128 * 128;
    const float* ablk = att_a  + (long)blk * NHEADS * 256;
    const float* rW   = resh_W + (long)blk * 512 * 128;
    const float* rb   = resh_b + (long)blk * 128;
    const int Zc = NHEADS * Bq;   // 32

    gemm32_k<64,0,true><<<dim3(1, 8, Zc), 256, SMEM64>>>(
        in,   BOff{Bq, (long)Nn*128, 0}, 128,
        Wblk, BOff{Bq, 0, 128*128},      128,
        nullptr, Z(),
        Wh, perZ((long)Nn*128), 128, 128,
        s1, s2, ablk);
    rowstat_k<<<(Zc*Nn)/8, 256>>>(s1, s2, mb, mI, zI);
    attgemm_k<2><<<dim3(4, Zc), 256, SMEMATT>>>(
        Wh, s1, s2, mI, zI, mb,
        hp2, BOff{Bq, (long)Nn*512, 128}, 512);
    gemm32_k<64,0,false><<<dim3(1, 64, 1), 256, SMEM64>>>(
        hp2, Z(), 512,
        rW,  Z(), 128,
        rb,  Z(),
        tmp, Z(), 128, 512, nullptr, nullptr, nullptr);
    ln_res_k<<<MROWS, 128>>>(tmp, in, out);
}

static void out_gat(const float* in, float* dst, int widx,
                    const unsigned* mb,
                    const float* out_W, const float* out_a,
                    float* Wh, float* s1, float* s2, float* mI, float* zI)
{
    const float* Wblk = out_W + (long)widx * 128 * 128;
    const float* ablk = out_a + (long)widx * 256;
    const int Zc = Bq;

    gemm32_k<64,0,true><<<dim3(1, 8, Zc), 256, SMEM64>>>(
        in,   perZ((long)Nn*128), 128,
        Wblk, Z(),                128,
        nullptr, Z(),
        Wh, perZ((long)Nn*128), 128, 128,
        s1, s2, ablk);
    rowstat_k<<<(Zc*Nn)/8, 256>>>(s1, s2, mb, mI, zI);
    attgemm_k<1><<<dim3(4, Zc), 256, SMEMATT>>>(
        Wh, s1, s2, mI, zI, mb,
        dst, perZ((long)Nn*128), 128);
}

extern "C" void kernel_launch(void* const* d_in, const int* in_sizes, int n_in,
                              void* d_out, int out_size)
{
    const float* x      = (const float*)d_in[0];
    const int*   adj    = (const int*)  d_in[1];
    const float* f1w1 = (const float*)d_in[3];  const float* f1b1 = (const float*)d_in[4];
    const float* f1w2 = (const float*)d_in[5];  const float* f1b2 = (const float*)d_in[6];
    const float* f2w1 = (const float*)d_in[7];  const float* f2b1 = (const float*)d_in[8];
    const float* f2w2 = (const float*)d_in[9];  const float* f2b2 = (const float*)d_in[10];
    const float* f3w1 = (const float*)d_in[11]; const float* f3b1 = (const float*)d_in[12];
    const float* f3w2 = (const float*)d_in[13]; const float* f3b2 = (const float*)d_in[14];
    const float* att_W  = (const float*)d_in[15];
    const float* att_a  = (const float*)d_in[16];
    const float* resh_W = (const float*)d_in[17];
    const float* resh_b = (const float*)d_in[18];
    const float* out_W  = (const float*)d_in[19];
    const float* out_a  = (const float*)d_in[20];
    const float* proj_W = (const float*)d_in[21];
    const float* proj_b = (const float*)d_in[22];
    float* out = (float*)d_out;

    static bool attr_done = false;
    if (!attr_done) {
        cudaFuncSetAttribute(gemm32_k<64,0,false>, cudaFuncAttributeMaxDynamicSharedMemorySize, SMEM64);
        cudaFuncSetAttribute(gemm32_k<64,1,false>, cudaFuncAttributeMaxDynamicSharedMemorySize, SMEM64);
        cudaFuncSetAttribute(gemm32_k<64,0,true>,  cudaFuncAttributeMaxDynamicSharedMemorySize, SMEM64);
        cudaFuncSetAttribute(attgemm_k<1>, cudaFuncAttributeMaxDynamicSharedMemorySize, SMEMATT);
        cudaFuncSetAttribute(attgemm_k<2>, cudaFuncAttributeMaxDynamicSharedMemorySize, SMEMATT);
        attr_done = true;
    }

    float *bufA, *bufB, *tmp, *hp2, *Wh, *s1, *s2, *mI, *zI, *hf, *ht;
    unsigned *mask, *maskT;
    cudaGetSymbolAddress((void**)&bufA, g_bufA);
    cudaGetSymbolAddress((void**)&bufB, g_bufB);
    cudaGetSymbolAddress((void**)&tmp,  g_tmp);
    cudaGetSymbolAddress((void**)&hp2,  g_hp2);
    cudaGetSymbolAddress((void**)&Wh,   g_Wh);
    cudaGetSymbolAddress((void**)&s1,   g_s1);
    cudaGetSymbolAddress((void**)&s2,   g_s2);
    cudaGetSymbolAddress((void**)&mI,   g_mI);
    cudaGetSymbolAddress((void**)&zI,   g_zI);
    cudaGetSymbolAddress((void**)&hf,   g_hf);
    cudaGetSymbolAddress((void**)&ht,   g_ht);
    cudaGetSymbolAddress((void**)&mask,  g_mask);
    cudaGetSymbolAddress((void**)&maskT, g_maskT);

    // masks
    maskbuild_k<<<dim3(Nn, Bq), 512>>>(adj, mask, maskT);

    // ---- FEL ----
    gemm32_k<64,1,false><<<dim3(1, 64, 1), 256, SMEM64>>>(x, Z(), 32,  f1w1, Z(), 128, f1b1, Z(), bufB, Z(), 128, 32, nullptr, nullptr, nullptr);
    gemm32_k<64,1,false><<<dim3(1, 64, 1), 256, SMEM64>>>(bufB, Z(), 128, f1w2, Z(), 128, f1b2, Z(), bufA, Z(), 128, 128, nullptr, nullptr, nullptr);
    gemm32_k<64,1,false><<<dim3(2, 64, 1), 256, SMEM64>>>(bufA, Z(), 128, f2w1, Z(), 256, f2b1, Z(), tmp,  Z(), 256, 128, nullptr, nullptr, nullptr);
    gemm32_k<64,1,false><<<dim3(1, 64, 1), 256, SMEM64>>>(tmp,  Z(), 256, f2w2, Z(), 128, f2b2, Z(), bufB, Z(), 128, 256, nullptr, nullptr, nullptr);
    ln_res_k<<<MROWS, 128>>>(bufB, bufA, bufA);
    gemm32_k<64,1,false><<<dim3(2, 64, 1), 256, SMEM64>>>(bufA, Z(), 128, f3w1, Z(), 256, f3b1, Z(), tmp,  Z(), 256, 128, nullptr, nullptr, nullptr);
    gemm32_k<64,0,false><<<dim3(1, 64, 1), 256, SMEM64>>>(tmp,  Z(), 256, f3w2, Z(), 128, f3b2, Z(), bufB, Z(), 128, 256, nullptr, nullptr, nullptr);
    ln_res_k<<<MROWS, 128>>>(bufB, bufA, bufA);

    // ---- forward chain (mask) ----
    for (int i = 0; i < 3; i++)
        attn_block(bufA, bufA, i, mask, att_W, att_a, resh_W, resh_b, Wh, hp2, tmp, s1, s2, mI, zI);
    out_gat(bufA, hf, 0, mask, out_W, out_a, Wh, s1, s2, mI, zI);

    // ---- transposed chain (mask_t), seeded from hf ----
    attn_block(hf,   bufB, 3, maskT, att_W, att_a, resh_W, resh_b, Wh, hp2, tmp, s1, s2, mI, zI);
    attn_block(bufB, bufB, 4, maskT, att_W, att_a, resh_W, resh_b, Wh, hp2, tmp, s1, s2, mI, zI);
    attn_block(bufB, bufB, 5, maskT, att_W, att_a, resh_W, resh_b, Wh, hp2, tmp, s1, s2, mI, zI);
    out_gat(bufB, ht, 1, maskT, out_W, out_a, Wh, s1, s2, mI, zI);

    // ---- readout ----
    final_k<<<Bq, 256>>>(hf, ht, proj_W, proj_b, out);
    (void)in_sizes; (void)n_in; (void)out_size;
}

// round 14
// speedup vs baseline: 2.2788x; 1.0139x over previous
#include <cuda_runtime.h>
#include <math.h>

#define Bq 8
#define Nn 512
#define NFEAT 32
#define NHID 128
#define NHEADS 4
#define MROWS (Bq*Nn)   // 4096

// ---------------- scratch (device globals; no allocation) ----------------
__device__ __align__(256) float g_bufA[MROWS*NHID];
__device__ __align__(256) float g_bufB[MROWS*NHID];
__device__ __align__(256) float g_hp2 [MROWS*NHEADS*NHID];          // [b,n,H*o]
__device__ __align__(256) float g_Wh  [NHEADS*Bq*Nn*NHID];          // [z,n,o]
__device__ __align__(256) float g_s1  [NHEADS*Bq*Nn];
__device__ __align__(256) float g_s2  [NHEADS*Bq*Nn];
__device__ __align__(256) float g_hf  [MROWS*NHID];
__device__ __align__(256) float g_ht  [MROWS*NHID];
__device__ __align__(256) unsigned g_mask [Bq*Nn*(Nn/32)];
__device__ __align__(256) unsigned g_maskT[Bq*Nn*(Nn/32)];

// ---------------- batched-offset descriptor ----------------
struct BOff { int mod; long inS; long outS; };
__device__ __forceinline__ long boff(BOff o, int z){
    return (long)(z % o.mod) * o.inS + (long)(z / o.mod) * o.outS;
}

// ---------------- tf32 helpers ----------------
__device__ __forceinline__ unsigned f2tf(float x){
    unsigned u; asm("cvt.rna.tf32.f32 %0, %1;" : "=r"(u) : "f"(x)); return u;
}
__device__ __forceinline__ void mma_tf32(
    float& c0, float& c1, float& c2, float& c3,
    unsigned a0, unsigned a1, unsigned a2, unsigned a3,
    unsigned b0, unsigned b1)
{
    asm volatile(
        "mma.sync.aligned.m16n8k8.row.col.f32.tf32.tf32.f32 "
        "{%0,%1,%2,%3}, {%4,%5,%6,%7}, {%8,%9}, {%0,%1,%2,%3};\n"
        : "+f"(c0), "+f"(c1), "+f"(c2), "+f"(c3)
        : "r"(a0), "r"(a1), "r"(a2), "r"(a3), "r"(b0), "r"(b1));
}

// ============================================================================
// Pipelined tf32 GEMM: C = act(A @ W + bias).  Block tile 64 x 128, k-tile 32.
// FUSE: also emits s1[i]=Wh[i,:]·a[:128], s2[i]=Wh[i,:]·a[128:]  (gridDim.x==1)
// ============================================================================
template<int ACT, bool FUSE>   // ACT: 0=none 1=lrelu
__global__ void __launch_bounds__(256) gemm32_k(
    const float* __restrict__ A, BOff ao, int ldA,
    const float* __restrict__ W, BOff wo, int ldW,
    const float* __restrict__ bias, BOff bo,
    float* __restrict__ C, BOff co, int ldC, int K,
    float* __restrict__ s1g, float* __restrict__ s2g,
    const float* __restrict__ a_base)
{
    constexpr int MT = 64, MTW = 2;
    extern __shared__ unsigned dsm[];
    unsigned (*As)[MT][36]  = (unsigned(*)[MT][36])dsm;
    unsigned (*Bs)[32][136] = (unsigned(*)[32][136])(dsm + 2*MT*36);
    __shared__ float s1p[MT], s2p[MT];

    int z = blockIdx.z;
    A += boff(ao, z); W += boff(wo, z); C += boff(co, z);
    if (bias) bias += boff(bo, z);

    int tid  = threadIdx.x;
    int lane = tid & 31, warp = tid >> 5;
    int wm = (warp >> 2) * 32;
    int wn = (warp & 3) * 32;
    int g = lane >> 2, tig = lane & 3;
    int m0 = blockIdx.y * MT, n0 = blockIdx.x * 128;

    int arow = tid >> 3, acol = (tid & 7) * 4;
    int brow = tid >> 5, bcol = (tid & 31) * 4;

    if (FUSE && tid < MT) { s1p[tid] = 0.f; s2p[tid] = 0.f; }

    float4 aR[MTW], bR[4];
    #pragma unroll
    for (int q = 0; q < MTW; q++)
        aR[q] = *(const float4*)&A[(long)(m0 + arow + q*32) * ldA + acol];
    #pragma unroll
    for (int q = 0; q < 4; q++)
        bR[q] = *(const float4*)&W[(long)(brow + q*8) * ldW + n0 + bcol];
    #pragma unroll
    for (int q = 0; q < MTW; q++) {
        unsigned u[4] = {f2tf(aR[q].x), f2tf(aR[q].y), f2tf(aR[q].z), f2tf(aR[q].w)};
        *(uint4*)&As[0][arow + q*32][acol] = *(uint4*)u;
    }
    #pragma unroll
    for (int q = 0; q < 4; q++) {
        unsigned u[4] = {f2tf(bR[q].x), f2tf(bR[q].y), f2tf(bR[q].z), f2tf(bR[q].w)};
        *(uint4*)&Bs[0][brow + q*8][bcol] = *(uint4*)u;
    }
    __syncthreads();

    float acc[MTW][4][4];
    #pragma unroll
    for (int mt = 0; mt < MTW; mt++)
        #pragma unroll
        for (int nt = 0; nt < 4; nt++)
            #pragma unroll
            for (int c = 0; c < 4; c++) acc[mt][nt][c] = 0.f;

    int nIter = K / 32;
    for (int it = 0; it < nIter; it++) {
        int cur = it & 1, nxt = cur ^ 1;
        if (it + 1 < nIter) {
            int k0 = (it + 1) * 32;
            #pragma unroll
            for (int q = 0; q < MTW; q++)
                aR[q] = *(const float4*)&A[(long)(m0 + arow + q*32) * ldA + k0 + acol];
            #pragma unroll
            for (int q = 0; q < 4; q++)
                bR[q] = *(const float4*)&W[(long)(k0 + brow + q*8) * ldW + n0 + bcol];
        }
        #pragma unroll
        for (int kk = 0; kk < 32; kk += 8) {
            unsigned bf[4][2];
            #pragma unroll
            for (int nt = 0; nt < 4; nt++) {
                bf[nt][0] = Bs[cur][kk + tig][wn + nt*8 + g];
                bf[nt][1] = Bs[cur][kk + tig + 4][wn + nt*8 + g];
            }
            #pragma unroll
            for (int mt = 0; mt < MTW; mt++) {
                int r0 = wm + mt*16 + g;
                unsigned a0 = As[cur][r0][kk + tig];
                unsigned a1 = As[cur][r0 + 8][kk + tig];
                unsigned a2 = As[cur][r0][kk + tig + 4];
                unsigned a3 = As[cur][r0 + 8][kk + tig + 4];
                #pragma unroll
                for (int nt = 0; nt < 4; nt++)
                    mma_tf32(acc[mt][nt][0], acc[mt][nt][1], acc[mt][nt][2], acc[mt][nt][3],
                             a0, a1, a2, a3, bf[nt][0], bf[nt][1]);
            }
        }
        if (it + 1 < nIter) {
            #pragma unroll
            for (int q = 0; q < MTW; q++) {
                unsigned u[4] = {f2tf(aR[q].x), f2tf(aR[q].y), f2tf(aR[q].z), f2tf(aR[q].w)};
                *(uint4*)&As[nxt][arow + q*32][acol] = *(uint4*)u;
            }
            #pragma unroll
            for (int q = 0; q < 4; q++) {
                unsigned u[4] = {f2tf(bR[q].x), f2tf(bR[q].y), f2tf(bR[q].z), f2tf(bR[q].w)};
                *(uint4*)&Bs[nxt][brow + q*8][bcol] = *(uint4*)u;
            }
        }
        __syncthreads();
    }

    #pragma unroll
    for (int mt = 0; mt < MTW; mt++) {
        int row0 = m0 + wm + mt*16 + g;
        #pragma unroll
        for (int nt = 0; nt < 4; nt++) {
            int col = n0 + wn + nt*8 + 2*tig;
            float b0 = bias ? bias[col] : 0.f;
            float b1 = bias ? bias[col + 1] : 0.f;
            float v[4] = {acc[mt][nt][0] + b0, acc[mt][nt][1] + b1,
                          acc[mt][nt][2] + b0, acc[mt][nt][3] + b1};
            #pragma unroll
            for (int c = 0; c < 4; c++)
                if (ACT == 1) v[c] = v[c] > 0.f ? v[c] : 0.01f * v[c];
            *(float2*)&C[(long)row0 * ldC + col]       = make_float2(v[0], v[1]);
            *(float2*)&C[(long)(row0 + 8) * ldC + col] = make_float2(v[2], v[3]);
        }
    }

    if (FUSE) {
        const float* av = a_base + (z / Bq) * 256;
        #pragma unroll
        for (int mt = 0; mt < MTW; mt++) {
            int rl = wm + mt*16 + g;
            float p1a = 0.f, p2a = 0.f, p1b = 0.f, p2b = 0.f;
            #pragma unroll
            for (int nt = 0; nt < 4; nt++) {
                int col = wn + nt*8 + 2*tig;
                float a10 = av[col], a11 = av[col+1];
                float a20 = av[128+col], a21 = av[128+col+1];
                p1a += acc[mt][nt][0]*a10 + acc[mt][nt][1]*a11;
                p2a += acc[mt][nt][0]*a20 + acc[mt][nt][1]*a21;
                p1b += acc[mt][nt][2]*a10 + acc[mt][nt][3]*a11;
                p2b += acc[mt][nt][2]*a20 + acc[mt][nt][3]*a21;
            }
            atomicAdd(&s1p[rl], p1a);     atomicAdd(&s2p[rl], p2a);
            atomicAdd(&s1p[rl + 8], p1b); atomicAdd(&s2p[rl + 8], p2b);
        }
        __syncthreads();
        if (tid < MT) {
            long row = (long)z * Nn + m0 + tid;
            s1g[row] = s1p[tid];
            s2g[row] = s2p[tid];
        }
    }
}

// ============================================================================
// Fused att-GEMM with in-kernel softmax stats.
// out = act( P @ Wh ),  P[i,j] = mask ? exp(lrelu(s1_i s2_j)-m_i)*zinv_i : 0
// Block tile 64 x 128, k-tile 32 over j. 256 threads. grid = (8, Zc).
// ============================================================================
template<int ACT>   // 1=lrelu 2=elu
__global__ void __launch_bounds__(256) attgemm_k(
    const float* __restrict__ Wh,
    const float* __restrict__ s1, const float* __restrict__ s2,
    const unsigned* __restrict__ maskbits,
    float* __restrict__ out, BOff co, int ldC)
{
    extern __shared__ unsigned dsm[];
    unsigned (*As)[64][36]  = (unsigned(*)[64][36])dsm;               // 2*64*36
    unsigned (*Bs)[32][136] = (unsigned(*)[32][136])(dsm + 2*64*36);  // 2*32*136
    float*    s2s = (float*)(dsm + 2*64*36 + 2*32*136);               // [512]
    float*    s1s = s2s + 512;                                        // [64]
    unsigned* mw  = (unsigned*)(s1s + 64);                            // [64*16]

    int z = blockIdx.y, b = z & 7;
    const float* whz = Wh + (long)z * Nn * NHID;
    float* outz = out + boff(co, z);
    int i0 = blockIdx.x * 64;

    int tid  = threadIdx.x;
    int lane = tid & 31, warp = tid >> 5;
    int wm = (warp >> 2) * 32, wn = (warp & 3) * 32;
    int g = lane >> 2, tig = lane & 3;
    int brow = tid >> 5, bcol = (tid & 31) * 4;

    // stage s2, s1, mask rows
    for (int t = tid; t < Nn; t += 256) s2s[t] = s2[(long)z * Nn + t];
    if (tid < 64) s1s[tid] = s1[(long)z * Nn + i0 + tid];
    for (int t = tid; t < 64*16; t += 256)
        mw[t] = maskbits[((long)b * Nn + i0 + (t >> 4)) * 16 + (t & 15)];
    __syncthreads();

    // ---- fused softmax stats: 4 threads per row, 128 j each ----
    int grow = tid >> 2, gpart = tid & 3;
    float gs1 = s1s[grow];
    const unsigned* gmw = &mw[grow * 16];
    float gmi, gzi;
    {
        int jb = gpart * 128;
        float m = -1e30f;
        for (int j = jb; j < jb + 128; j++) {
            if ((gmw[j >> 5] >> (j & 31)) & 1) {
                float v = gs1 * s2s[j];
                v = v > 0.f ? v : 0.01f * v;
                if (v > m) m = v;
            }
        }
        m = fmaxf(m, __shfl_xor_sync(~0u, m, 1));
        m = fmaxf(m, __shfl_xor_sync(~0u, m, 2));
        if (m < -1e29f) m = 0.f;
        float s = 0.f;
        for (int j = jb; j < jb + 128; j++) {
            if ((gmw[j >> 5] >> (j & 31)) & 1) {
                float v = gs1 * s2s[j];
                v = v > 0.f ? v : 0.01f * v;
                s += __expf(v - m);
            }
        }
        s += __shfl_xor_sync(~0u, s, 1);
        s += __shfl_xor_sync(~0u, s, 2);
        gmi = m; gzi = s > 0.f ? 1.f / s : 0.f;
    }

    // prologue: As[0] generation + Bs[0] load
    {
        unsigned word = gmw[0];
        #pragma unroll
        for (int u = 0; u < 8; u++) {
            int jj = gpart*8 + u;
            float v = gs1 * s2s[jj];
            v = v > 0.f ? v : 0.01f * v;
            float p = ((word >> jj) & 1) ? __expf(v - gmi) * gzi : 0.f;
            As[0][grow][jj] = f2tf(p);
        }
        float4 bR[4];
        #pragma unroll
        for (int q = 0; q < 4; q++)
            bR[q] = *(const float4*)&whz[(long)(brow + q*8) * NHID + bcol];
        #pragma unroll
        for (int q = 0; q < 4; q++) {
            unsigned u[4] = {f2tf(bR[q].x), f2tf(bR[q].y), f2tf(bR[q].z), f2tf(bR[q].w)};
            *(uint4*)&Bs[0][brow + q*8][bcol] = *(uint4*)u;
        }
    }
    __syncthreads();

    float acc[2][4][4];
    #pragma unroll
    for (int mt = 0; mt < 2; mt++)
        #pragma unroll
        for (int nt = 0; nt < 4; nt++)
            #pragma unroll
            for (int c = 0; c < 4; c++) acc[mt][nt][c] = 0.f;

    const int nIter = Nn / 32;   // 16
    for (int it = 0; it < nIter; it++) {
        int cur = it & 1, nxt = cur ^ 1;
        float4 bR[4];
        if (it + 1 < nIter) {
            int j0 = (it + 1) * 32;
            #pragma unroll
            for (int q = 0; q < 4; q++)
                bR[q] = *(const float4*)&whz[(long)(j0 + brow + q*8) * NHID + bcol];
        }
        #pragma unroll
        for (int kk = 0; kk < 32; kk += 8) {
            unsigned bf[4][2];
            #pragma unroll
            for (int nt = 0; nt < 4; nt++) {
                bf[nt][0] = Bs[cur][kk + tig][wn + nt*8 + g];
                bf[nt][1] = Bs[cur][kk + tig + 4][wn + nt*8 + g];
            }
            #pragma unroll
            for (int mt = 0; mt < 2; mt++) {
                int r0 = wm + mt*16 + g;
                unsigned a0 = As[cur][r0][kk + tig];
                unsigned a1 = As[cur][r0 + 8][kk + tig];
                unsigned a2 = As[cur][r0][kk + tig + 4];
                unsigned a3 = As[cur][r0 + 8][kk + tig + 4];
                #pragma unroll
                for (int nt = 0; nt < 4; nt++)
                    mma_tf32(acc[mt][nt][0], acc[mt][nt][1], acc[mt][nt][2], acc[mt][nt][3],
                             a0, a1, a2, a3, bf[nt][0], bf[nt][1]);
            }
        }
        if (it + 1 < nIter) {
            int j0 = (it + 1) * 32;
            unsigned word = gmw[j0 >> 5];
            #pragma unroll
            for (int u = 0; u < 8; u++) {
                int jj = gpart*8 + u;
                float v = gs1 * s2s[j0 + jj];
                v = v > 0.f ? v : 0.01f * v;
                float p = ((word >> jj) & 1) ? __expf(v - gmi) * gzi : 0.f;
                As[nxt][grow][jj] = f2tf(p);
            }
            #pragma unroll
            for (int q = 0; q < 4; q++) {
                unsigned u[4] = {f2tf(bR[q].x), f2tf(bR[q].y), f2tf(bR[q].z), f2tf(bR[q].w)};
                *(uint4*)&Bs[nxt][brow + q*8][bcol] = *(uint4*)u;
            }
        }
        __syncthreads();
    }

    #pragma unroll
    for (int mt = 0; mt < 2; mt++) {
        int row0 = i0 + wm + mt*16 + g;
        #pragma unroll
        for (int nt = 0; nt < 4; nt++) {
            int col = wn + nt*8 + 2*tig;
            float v[4] = {acc[mt][nt][0], acc[mt][nt][1], acc[mt][nt][2], acc[mt][nt][3]};
            #pragma unroll
            for (int c = 0; c < 4; c++) {
                if (ACT == 1) v[c] = v[c] > 0.f ? v[c] : 0.01f * v[c];
                else if (ACT == 2) v[c] = v[c] > 0.f ? v[c] : (expf(v[c]) - 1.f);
            }
            *(float2*)&outz[(long)row0 * ldC + col]       = make_float2(v[0], v[1]);
            *(float2*)&outz[(long)(row0 + 8) * ldC + col] = make_float2(v[2], v[3]);
        }
    }
}

// ============================================================================
// resh GEMM + bias + residual + LayerNorm fused.
// out = LN( hp2 @ rW + rb + res ).  Block = 64 rows, full 128 cols. grid 64.
// ============================================================================
__global__ void __launch_bounds__(256) resh_ln_k(
    const float* __restrict__ A,          // hp2 [4096 x 512]
    const float* __restrict__ W,          // rW  [512 x 128]
    const float* __restrict__ bias,       // rb  [128]
    const float* __restrict__ res,        // residual [4096 x 128]
    float* __restrict__ out)              // [4096 x 128]
{
    extern __shared__ unsigned dsm[];
    unsigned (*As)[64][36]  = (unsigned(*)[64][36])dsm;
    unsigned (*Bs)[32][136] = (unsigned(*)[32][136])(dsm + 2*64*36);
    float*    S = (float*)(dsm + 2*64*36 + 2*32*136);   // [64][132]

    int tid  = threadIdx.x;
    int lane = tid & 31, warp = tid >> 5;
    int wm = (warp >> 2) * 32, wn = (warp & 3) * 32;
    int g = lane >> 2, tig = lane & 3;
    int m0 = blockIdx.x * 64;

    int arow = tid >> 3, acol = (tid & 7) * 4;
    int brow = tid >> 5, bcol = (tid & 31) * 4;

    float4 aR[2], bR[4];
    #pragma unroll
    for (int q = 0; q < 2; q++)
        aR[q] = *(const float4*)&A[(long)(m0 + arow + q*32) * 512 + acol];
    #pragma unroll
    for (int q = 0; q < 4; q++)
        bR[q] = *(const float4*)&W[(long)(brow + q*8) * 128 + bcol];
    #pragma unroll
    for (int q = 0; q < 2; q++) {
        unsigned u[4] = {f2tf(aR[q].x), f2tf(aR[q].y), f2tf(aR[q].z), f2tf(aR[q].w)};
        *(uint4*)&As[0][arow + q*32][acol] = *(uint4*)u;
    }
    #pragma unroll
    for (int q = 0; q < 4; q++) {
        unsigned u[4] = {f2tf(bR[q].x), f2tf(bR[q].y), f2tf(bR[q].z), f2tf(bR[q].w)};
        *(uint4*)&Bs[0][brow + q*8][bcol] = *(uint4*)u;
    }
    __syncthreads();

    float acc[2][4][4];
    #pragma unroll
    for (int mt = 0; mt < 2; mt++)
        #pragma unroll
        for (int nt = 0; nt < 4; nt++)
            #pragma unroll
            for (int c = 0; c < 4; c++) acc[mt][nt][c] = 0.f;

    const int nIter = 512 / 32;  // 16
    for (int it = 0; it < nIter; it++) {
        int cur = it & 1, nxt = cur ^ 1;
        if (it + 1 < nIter) {
            int k0 = (it + 1) * 32;
            #pragma unroll
            for (int q = 0; q < 2; q++)
                aR[q] = *(const float4*)&A[(long)(m0 + arow + q*32) * 512 + k0 + acol];
            #pragma unroll
            for (int q = 0; q < 4; q++)
                bR[q] = *(const float4*)&W[(long)(k0 + brow + q*8) * 128 + bcol];
        }
        #pragma unroll
        for (int kk = 0; kk < 32; kk += 8) {
            unsigned bf[4][2];
            #pragma unroll
            for (int nt = 0; nt < 4; nt++) {
                bf[nt][0] = Bs[cur][kk + tig][wn + nt*8 + g];
                bf[nt][1] = Bs[cur][kk + tig + 4][wn + nt*8 + g];
            }
            #pragma unroll
            for (int mt = 0; mt < 2; mt++) {
                int r0 = wm + mt*16 + g;
                unsigned a0 = As[cur][r0][kk + tig];
                unsigned a1 = As[cur][r0 + 8][kk + tig];
                unsigned a2 = As[cur][r0][kk + tig + 4];
                unsigned a3 = As[cur][r0 + 8][kk + tig + 4];
                #pragma unroll
                for (int nt = 0; nt < 4; nt++)
                    mma_tf32(acc[mt][nt][0], acc[mt][nt][1], acc[mt][nt][2], acc[mt][nt][3],
                             a0, a1, a2, a3, bf[nt][0], bf[nt][1]);
            }
        }
        if (it + 1 < nIter) {
            #pragma unroll
            for (int q = 0; q < 2; q++) {
                unsigned u[4] = {f2tf(aR[q].x), f2tf(aR[q].y), f2tf(aR[q].z), f2tf(aR[q].w)};
                *(uint4*)&As[nxt][arow + q*32][acol] = *(uint4*)u;
            }
            #pragma unroll
            for (int q = 0; q < 4; q++) {
                unsigned u[4] = {f2tf(bR[q].x), f2tf(bR[q].y), f2tf(bR[q].z), f2tf(bR[q].w)};
                *(uint4*)&Bs[nxt][brow + q*8][bcol] = *(uint4*)u;
            }
        }
        __syncthreads();
    }

    // stage acc + bias into S
    #pragma unroll
    for (int mt = 0; mt < 2; mt++) {
        int rl = wm + mt*16 + g;
        #pragma unroll
        for (int nt = 0; nt < 4; nt++) {
            int col = wn + nt*8 + 2*tig;
            float b0 = bias[col], b1 = bias[col + 1];
            S[rl*132 + col]     = acc[mt][nt][0] + b0;
            S[rl*132 + col+1]   = acc[mt][nt][1] + b1;
            S[(rl+8)*132 + col]   = acc[mt][nt][2] + b0;
            S[(rl+8)*132 + col+1] = acc[mt][nt][3] + b1;
        }
    }
    __syncthreads();

    // LN with residual: 4 threads per row, 32 cols each
    {
        int row = tid >> 2, part = tid & 3;
        int c0 = part * 32;
        float v[32];
        float s = 0.f;
        #pragma unroll
        for (int q = 0; q < 8; q++) {
            float4 r4 = *(const float4*)&res[(long)(m0 + row) * 128 + c0 + q*4];
            v[q*4+0] = S[row*132 + c0 + q*4+0] + r4.x;
            v[q*4+1] = S[row*132 + c0 + q*4+1] + r4.y;
            v[q*4+2] = S[row*132 + c0 + q*4+2] + r4.z;
            v[q*4+3] = S[row*132 + c0 + q*4+3] + r4.w;
            s += v[q*4+0] + v[q*4+1] + v[q*4+2] + v[q*4+3];
        }
        s += __shfl_xor_sync(~0u, s, 1);
        s += __shfl_xor_sync(~0u, s, 2);
        float mean = s * (1.f/128.f);
        float var = 0.f;
        #pragma unroll
        for (int k = 0; k < 32; k++) { float d = v[k] - mean; var += d*d; }
        var += __shfl_xor_sync(~0u, var, 1);
        var += __shfl_xor_sync(~0u, var, 2);
        float inv = rsqrtf(var * (1.f/128.f) + 1e-5f);
        #pragma unroll
        for (int q = 0; q < 8; q++) {
            float4 o4 = make_float4((v[q*4+0]-mean)*inv, (v[q*4+1]-mean)*inv,
                                    (v[q*4+2]-mean)*inv, (v[q*4+3]-mean)*inv);
            *(float4*)&out[(long)(m0 + row) * 128 + c0 + q*4] = o4;
        }
    }
}

// ============================================================================
// FEL megakernel: the whole 6-GEMM + 2-LN MLP, row-local, one launch.
// grid 64 blocks x 64 rows, activations in smem.
// LDS0 = 260: divisible by 4 (16B-aligned float4 rows), 260 % 32 = 4 words
// per-row bank shift -> conflict-free column reads.
// ============================================================================
#define LDS0 260

__device__ __forceinline__ void fel_layer(
    const float* __restrict__ Sin,        // smem act, ld LDS0
    const float* __restrict__ W,          // global [K x Nout]
    const float* __restrict__ bias,       // global [Nout]
    int K, int Nout, bool act,
    float* __restrict__ Sout, int ldOut,  // smem
    unsigned* __restrict__ Wb)            // smem [32*136]
{
    int tid  = threadIdx.x;
    int lane = tid & 31, warp = tid >> 5;
    int wm = (warp >> 2) * 32, wn = (warp & 3) * 32;
    int g = lane >> 2, tig = lane & 3;
    int brow = tid >> 5, bcol = (tid & 31) * 4;

    for (int nc = 0; nc < Nout; nc += 128) {
        float acc[2][4][4];
        #pragma unroll
        for (int mt = 0; mt < 2; mt++)
            #pragma unroll
            for (int nt = 0; nt < 4; nt++)
                #pragma unroll
                for (int c = 0; c < 4; c++) acc[mt][nt][c] = 0.f;

        for (int k0 = 0; k0 < K; k0 += 32) {
            #pragma unroll
            for (int q = 0; q < 4; q++) {
                float4 v = *(const float4*)&W[(long)(k0 + brow + q*8) * Nout + nc + bcol];
                unsigned u[4] = {f2tf(v.x), f2tf(v.y), f2tf(v.z), f2tf(v.w)};
                *(uint4*)&Wb[(brow + q*8)*136 + bcol] = *(uint4*)u;
            }
            __syncthreads();
            #pragma unroll
            for (int kk = 0; kk < 32; kk += 8) {
                unsigned bf[4][2];
                #pragma unroll
                for (int nt = 0; nt < 4; nt++) {
                    bf[nt][0] = Wb[(kk + tig)*136 + wn + nt*8 + g];
                    bf[nt][1] = Wb[(kk + tig + 4)*136 + wn + nt*8 + g];
                }
                #pragma unroll
                for (int mt = 0; mt < 2; mt++) {
                    int r0 = wm + mt*16 + g;
                    unsigned a0 = f2tf(Sin[r0*LDS0 + k0 + kk + tig]);
                    unsigned a1 = f2tf(Sin[(r0+8)*LDS0 + k0 + kk + tig]);
                    unsigned a2 = f2tf(Sin[r0*LDS0 + k0 + kk + tig + 4]);
                    unsigned a3 = f2tf(Sin[(r0+8)*LDS0 + k0 + kk + tig + 4]);
                    #pragma unroll
                    for (int nt = 0; nt < 4; nt++)
                        mma_tf32(acc[mt][nt][0], acc[mt][nt][1], acc[mt][nt][2], acc[mt][nt][3],
                                 a0, a1, a2, a3, bf[nt][0], bf[nt][1]);
                }
            }
            __syncthreads();
        }
        #pragma unroll
        for (int mt = 0; mt < 2; mt++) {
            int r0 = wm + mt*16 + g;
            #pragma unroll
            for (int nt = 0; nt < 4; nt++) {
                int col = nc + wn + nt*8 + 2*tig;
                float b0 = bias[col], b1 = bias[col+1];
                float v0 = acc[mt][nt][0]+b0, v1 = acc[mt][nt][1]+b1;
                float v2 = acc[mt][nt][2]+b0, v3 = acc[mt][nt][3]+b1;
                if (act) {
                    v0 = v0 > 0.f ? v0 : 0.01f*v0; v1 = v1 > 0.f ? v1 : 0.01f*v1;
                    v2 = v2 > 0.f ? v2 : 0.01f*v2; v3 = v3 > 0.f ? v3 : 0.01f*v3;
                }
                Sout[r0*ldOut + col] = v0;     Sout[r0*ldOut + col+1] = v1;
                Sout[(r0+8)*ldOut + col] = v2; Sout[(r0+8)*ldOut + col+1] = v3;
            }
        }
        __syncthreads();
    }
}

__device__ __forceinline__ void fel_ln(
    const float* __restrict__ Sh, int ldH,
    const float* __restrict__ Sres, int ldR,
    float* __restrict__ dst, int ldD)
{
    int tid = threadIdx.x;
    int row = tid >> 2, part = tid & 3;
    int c0 = part * 32;
    float v[32];
    float s = 0.f;
    #pragma unroll
    for (int k = 0; k < 32; k++) {
        v[k] = Sh[row*ldH + c0 + k] + Sres[row*ldR + c0 + k];
        s += v[k];
    }
    s += __shfl_xor_sync(~0u, s, 1);
    s += __shfl_xor_sync(~0u, s, 2);
    float mean = s * (1.f/128.f);
    float var = 0.f;
    #pragma unroll
    for (int k = 0; k < 32; k++) { float d = v[k]-mean; var += d*d; }
    var += __shfl_xor_sync(~0u, var, 1);
    var += __shfl_xor_sync(~0u, var, 2);
    float inv = rsqrtf(var * (1.f/128.f) + 1e-5f);
    #pragma unroll
    for (int k = 0; k < 32; k++)
        dst[row*ldD + c0 + k] = (v[k]-mean)*inv;
    __syncthreads();
}

__global__ void __launch_bounds__(256) fel_k(
    const float* __restrict__ x,
    const float* __restrict__ f1w1, const float* __restrict__ f1b1,
    const float* __restrict__ f1w2, const float* __restrict__ f1b2,
    const float* __restrict__ f2w1, const float* __restrict__ f2b1,
    const float* __restrict__ f2w2, const float* __restrict__ f2b2,
    const float* __restrict__ f3w1, const float* __restrict__ f3b1,
    const float* __restrict__ f3w2, const float* __restrict__ f3b2,
    float* __restrict__ out)
{
    extern __shared__ float fsm[];
    float* S0 = fsm;                    // [64][LDS0]
    float* S1 = S0 + 64*LDS0;           // [64][LDS0]
    float* S2 = S1 + 64*LDS0;           // [64][132]
    unsigned* Wb = (unsigned*)(S2 + 64*132);   // [32*136]

    int tid = threadIdx.x;
    int m0 = blockIdx.x * 64;

    // load x rows (64 x 32)
    for (int i = tid; i < 64*32/4; i += 256) {
        float4 v = *(const float4*)&x[(long)m0*32 + i*4];
        int row = (i*4) >> 5, col = (i*4) & 31;
        *(float4*)&S0[row*LDS0 + col] = v;
    }
    __syncthreads();

    fel_layer(S0, f1w1, f1b1, 32,  128, true,  S1, LDS0, Wb);
    fel_layer(S1, f1w2, f1b2, 128, 128, true,  S0, LDS0, Wb);   // res in S0
    fel_layer(S0, f2w1, f2b1, 128, 256, true,  S1, LDS0, Wb);
    fel_layer(S1, f2w2, f2b2, 256, 128, true,  S2, 132, Wb);
    fel_ln(S2, 132, S0, LDS0, S1, LDS0);                         // x2 in S1
    fel_layer(S1, f3w1, f3b1, 128, 256, true,  S0, LDS0, Wb);
    fel_layer(S0, f3w2, f3b2, 256, 128, false, S2, 132, Wb);
    fel_ln(S2, 132, S1, LDS0, out + (long)m0*128, 128);
}

// ---------------- adjacency -> packed bitmask (normal + transposed) ----------------
__global__ void maskbuild_k(const int* __restrict__ adj,
                            unsigned* __restrict__ mb, unsigned* __restrict__ mbT)
{
    int i = blockIdx.x, b = blockIdx.y, j = threadIdx.x;
    int lane = j & 31, w = j >> 5;
    unsigned bit  = adj[((long)b * Nn + i) * Nn + j] > 0;
    unsigned word = __ballot_sync(~0u, bit);
    if (!lane) mb[((long)b * Nn + i) * 16 + w] = word;
    unsigned bitT  = adj[((long)b * Nn + j) * Nn + i] > 0;
    unsigned wordT = __ballot_sync(~0u, bitT);
    if (!lane) mbT[((long)b * Nn + i) * 16 + w] = wordT;
}

// ---------------- final: out[b] = mean_n concat(hf,ht) . proj_W + proj_b ----------------
__global__ void final_k(const float* __restrict__ hf, const float* __restrict__ ht,
                        const float* __restrict__ pW, const float* __restrict__ pb,
                        float* __restrict__ out)
{
    int b = blockIdx.x, t = threadIdx.x;
    const float* src = (t < 128) ? hf : ht;
    int f = t & 127;
    float w = pW[t];
    float acc = 0.f;
    for (int n = 0; n < Nn; n++) acc += src[((long)b * Nn + n) * 128 + f];
    acc *= w;
    __shared__ float red[8];
    for (int off = 16; off; off >>= 1) acc += __shfl_xor_sync(~0u, acc, off);
    if ((t & 31) == 0) red[t >> 5] = acc;
    __syncthreads();
    if (t == 0) {
        float s = 0.f;
        #pragma unroll
        for (int k = 0; k < 8; k++) s += red[k];
        out[b] = s / (float)Nn + pb[0];
    }
}

// ---------------- host orchestration ----------------
static inline BOff Z()            { return BOff{1, 0, 0}; }
static inline BOff perZ(long s)   { return BOff{1, 0, s}; }

#define SMEMG    ((2*64*36 + 2*32*136) * 4)                         // 53248
#define SMEMATT  ((2*64*36 + 2*32*136 + 512 + 64) * 4 + 64*16*4)    // 59648
#define SMEMRESH (SMEMG + 64*132*4)                                  // 87040
#define SMEMFEL  ((64*LDS0*2 + 64*132) * 4 + 32*136*4)               // 184320

static void attn_block(const float* in, float* out, int blk,
                       const unsigned* mb,
                       const float* att_W, const float* att_a,
                       const float* resh_W, const float* resh_b,
                       float* Wh, float* hp2, float* s1, float* s2)
{
    const float* Wblk = att_W  + (long)blk * NHEADS * 128 * 128;
    const float* ablk = att_a  + (long)blk * NHEADS * 256;
    const float* rW   = resh_W + (long)blk * 512 * 128;
    const float* rb   = resh_b + (long)blk * 128;
    const int Zc = NHEADS * Bq;   // 32

    gemm32_k<0,true><<<dim3(1, 8, Zc), 256, SMEMG>>>(
        in,   BOff{Bq, (long)Nn*128, 0}, 128,
        Wblk, BOff{Bq, 0, 128*128},      128,
        nullptr, Z(),
        Wh, perZ((long)Nn*128), 128, 128,
        s1, s2, ablk);
    attgemm_k<2><<<dim3(8, Zc), 256, SMEMATT>>>(
        Wh, s1, s2, mb, hp2, BOff{Bq, (long)Nn*512, 128}, 512);
    resh_ln_k<<<64, 256, SMEMRESH>>>(hp2, rW, rb, in, out);
}

static void out_gat(const float* in, float* dst, int widx,
                    const unsigned* mb,
                    const float* out_W, const float* out_a,
                    float* Wh, float* s1, float* s2)
{
    const float* Wblk = out_W + (long)widx * 128 * 128;
    const float* ablk = out_a + (long)widx * 256;
    const int Zc = Bq;

    gemm32_k<0,true><<<dim3(1, 8, Zc), 256, SMEMG>>>(
        in,   perZ((long)Nn*128), 128,
        Wblk, Z(),                128,
        nullptr, Z(),
        Wh, perZ((long)Nn*128), 128, 128,
        s1, s2, ablk);
    attgemm_k<1><<<dim3(8, Zc), 256, SMEMATT>>>(
        Wh, s1, s2, mb, dst, perZ((long)Nn*128), 128);
}

extern "C" void kernel_launch(void* const* d_in, const int* in_sizes, int n_in,
                              void* d_out, int out_size)
{
    const float* x      = (const float*)d_in[0];
    const int*   adj    = (const int*)  d_in[1];
    const float* f1w1 = (const float*)d_in[3];  const float* f1b1 = (const float*)d_in[4];
    const float* f1w2 = (const float*)d_in[5];  const float* f1b2 = (const float*)d_in[6];
    const float* f2w1 = (const float*)d_in[7];  const float* f2b1 = (const float*)d_in[8];
    const float* f2w2 = (const float*)d_in[9];  const float* f2b2 = (const float*)d_in[10];
    const float* f3w1 = (const float*)d_in[11]; const float* f3b1 = (const float*)d_in[12];
    const float* f3w2 = (const float*)d_in[13]; const float* f3b2 = (const float*)d_in[14];
    const float* att_W  = (const float*)d_in[15];
    const float* att_a  = (const float*)d_in[16];
    const float* resh_W = (const float*)d_in[17];
    const float* resh_b = (const float*)d_in[18];
    const float* out_W  = (const float*)d_in[19];
    const float* out_a  = (const float*)d_in[20];
    const float* proj_W = (const float*)d_in[21];
    const float* proj_b = (const float*)d_in[22];
    float* out = (float*)d_out;

    static bool attr_done = false;
    if (!attr_done) {
        cudaFuncSetAttribute(gemm32_k<0,false>, cudaFuncAttributeMaxDynamicSharedMemorySize, SMEMG);
        cudaFuncSetAttribute(gemm32_k<0,true>,  cudaFuncAttributeMaxDynamicSharedMemorySize, SMEMG);
        cudaFuncSetAttribute(attgemm_k<1>, cudaFuncAttributeMaxDynamicSharedMemorySize, SMEMATT);
        cudaFuncSetAttribute(attgemm_k<2>, cudaFuncAttributeMaxDynamicSharedMemorySize, SMEMATT);
        cudaFuncSetAttribute(resh_ln_k, cudaFuncAttributeMaxDynamicSharedMemorySize, SMEMRESH);
        cudaFuncSetAttribute(fel_k, cudaFuncAttributeMaxDynamicSharedMemorySize, SMEMFEL);
        attr_done = true;
    }

    float *bufA, *bufB, *hp2, *Wh, *s1, *s2, *hf, *ht;
    unsigned *mask, *maskT;
    cudaGetSymbolAddress((void**)&bufA, g_bufA);
    cudaGetSymbolAddress((void**)&bufB, g_bufB);
    cudaGetSymbolAddress((void**)&hp2,  g_hp2);
    cudaGetSymbolAddress((void**)&Wh,   g_Wh);
    cudaGetSymbolAddress((void**)&s1,   g_s1);
    cudaGetSymbolAddress((void**)&s2,   g_s2);
    cudaGetSymbolAddress((void**)&hf,   g_hf);
    cudaGetSymbolAddress((void**)&ht,   g_ht);
    cudaGetSymbolAddress((void**)&mask,  g_mask);
    cudaGetSymbolAddress((void**)&maskT, g_maskT);

    // masks
    maskbuild_k<<<dim3(Nn, Bq), 512>>>(adj, mask, maskT);

    // ---- FEL (single megakernel) ----
    fel_k<<<64, 256, SMEMFEL>>>(x, f1w1, f1b1, f1w2, f1b2,
                                f2w1, f2b1, f2w2, f2b2,
                                f3w1, f3b1, f3w2, f3b2, bufA);

    // ---- forward chain (mask) ----
    for (int i = 0; i < 3; i++)
        attn_block(bufA, bufA, i, mask, att_W, att_a, resh_W, resh_b, Wh, hp2, s1, s2);
    out_gat(bufA, hf, 0, mask, out_W, out_a, Wh, s1, s2);

    // ---- transposed chain (mask_t), seeded from hf ----
    attn_block(hf,   bufB, 3, maskT, att_W, att_a, resh_W, resh_b, Wh, hp2, s1, s2);
    attn_block(bufB, bufB, 4, maskT, att_W, att_a, resh_W, resh_b, Wh, hp2, s1, s2);
    attn_block(bufB, bufB, 5, maskT, att_W, att_a, resh_W, resh_b, Wh, hp2, s1, s2);
    out_gat(bufB, ht, 1, maskT, out_W, out_a, Wh, s1, s2);

    // ---- readout ----
    final_k<<<Bq, 256>>>(hf, ht, proj_W, proj_b, out);
    (void)in_sizes; (void)n_in; (void)out_size;
}

// round 16
// speedup vs baseline: 3.0909x; 1.3564x over previous
#include <cuda_runtime.h>
#include <math.h>

#define Bq 8
#define Nn 512
#define NFEAT 32
#define NHID 128
#define NHEADS 4
#define MROWS (Bq*Nn)   // 4096

// ---------------- scratch (device globals; no allocation) ----------------
__device__ __align__(256) float g_bufA[MROWS*NHID];
__device__ __align__(256) float g_bufB[MROWS*NHID];
__device__ __align__(256) float g_hp2 [MROWS*NHEADS*NHID];          // [b,n,H*o]
__device__ __align__(256) float g_Wh  [NHEADS*Bq*Nn*NHID];          // [z,n,o]
__device__ __align__(256) float g_s1  [NHEADS*Bq*Nn];
__device__ __align__(256) float g_s2  [NHEADS*Bq*Nn];
__device__ __align__(256) float g_hf  [MROWS*NHID];
__device__ __align__(256) float g_ht  [MROWS*NHID];
__device__ __align__(256) unsigned g_mask [Bq*Nn*(Nn/32)];
__device__ __align__(256) unsigned g_maskT[Bq*Nn*(Nn/32)];

// ---------------- batched-offset descriptor ----------------
struct BOff { int mod; long inS; long outS; };
__device__ __forceinline__ long boff(BOff o, int z){
    return (long)(z % o.mod) * o.inS + (long)(z / o.mod) * o.outS;
}

// ---------------- tf32 helpers ----------------
__device__ __forceinline__ unsigned f2tf(float x){
    unsigned u; asm("cvt.rna.tf32.f32 %0, %1;" : "=r"(u) : "f"(x)); return u;
}
__device__ __forceinline__ void mma_tf32(
    float& c0, float& c1, float& c2, float& c3,
    unsigned a0, unsigned a1, unsigned a2, unsigned a3,
    unsigned b0, unsigned b1)
{
    asm volatile(
        "mma.sync.aligned.m16n8k8.row.col.f32.tf32.tf32.f32 "
        "{%0,%1,%2,%3}, {%4,%5,%6,%7}, {%8,%9}, {%0,%1,%2,%3};\n"
        : "+f"(c0), "+f"(c1), "+f"(c2), "+f"(c3)
        : "r"(a0), "r"(a1), "r"(a2), "r"(a3), "r"(b0), "r"(b1));
}

// ============================================================================
// Pipelined tf32 GEMM: C = act(A @ W + bias).  Block tile 64 x 128, k-tile 32.
// FUSE: also emits s1[i]=Wh[i,:]·a[:128], s2[i]=Wh[i,:]·a[128:]  (gridDim.x==1)
// ============================================================================
template<int ACT, bool FUSE>   // ACT: 0=none 1=lrelu
__global__ void __launch_bounds__(256) gemm32_k(
    const float* __restrict__ A, BOff ao, int ldA,
    const float* __restrict__ W, BOff wo, int ldW,
    const float* __restrict__ bias, BOff bo,
    float* __restrict__ C, BOff co, int ldC, int K,
    float* __restrict__ s1g, float* __restrict__ s2g,
    const float* __restrict__ a_base)
{
    constexpr int MT = 64, MTW = 2;
    extern __shared__ unsigned dsm[];
    unsigned (*As)[MT][36]  = (unsigned(*)[MT][36])dsm;
    unsigned (*Bs)[32][136] = (unsigned(*)[32][136])(dsm + 2*MT*36);
    __shared__ float s1p[MT], s2p[MT];

    int z = blockIdx.z;
    A += boff(ao, z); W += boff(wo, z); C += boff(co, z);
    if (bias) bias += boff(bo, z);

    int tid  = threadIdx.x;
    int lane = tid & 31, warp = tid >> 5;
    int wm = (warp >> 2) * 32;
    int wn = (warp & 3) * 32;
    int g = lane >> 2, tig = lane & 3;
    int m0 = blockIdx.y * MT, n0 = blockIdx.x * 128;

    int arow = tid >> 3, acol = (tid & 7) * 4;
    int brow = tid >> 5, bcol = (tid & 31) * 4;

    if (FUSE && tid < MT) { s1p[tid] = 0.f; s2p[tid] = 0.f; }

    float4 aR[MTW], bR[4];
    #pragma unroll
    for (int q = 0; q < MTW; q++)
        aR[q] = *(const float4*)&A[(long)(m0 + arow + q*32) * ldA + acol];
    #pragma unroll
    for (int q = 0; q < 4; q++)
        bR[q] = *(const float4*)&W[(long)(brow + q*8) * ldW + n0 + bcol];
    #pragma unroll
    for (int q = 0; q < MTW; q++) {
        unsigned u[4] = {f2tf(aR[q].x), f2tf(aR[q].y), f2tf(aR[q].z), f2tf(aR[q].w)};
        *(uint4*)&As[0][arow + q*32][acol] = *(uint4*)u;
    }
    #pragma unroll
    for (int q = 0; q < 4; q++) {
        unsigned u[4] = {f2tf(bR[q].x), f2tf(bR[q].y), f2tf(bR[q].z), f2tf(bR[q].w)};
        *(uint4*)&Bs[0][brow + q*8][bcol] = *(uint4*)u;
    }
    __syncthreads();

    float acc[MTW][4][4];
    #pragma unroll
    for (int mt = 0; mt < MTW; mt++)
        #pragma unroll
        for (int nt = 0; nt < 4; nt++)
            #pragma unroll
            for (int c = 0; c < 4; c++) acc[mt][nt][c] = 0.f;

    int nIter = K / 32;
    for (int it = 0; it < nIter; it++) {
        int cur = it & 1, nxt = cur ^ 1;
        if (it + 1 < nIter) {
            int k0 = (it + 1) * 32;
            #pragma unroll
            for (int q = 0; q < MTW; q++)
                aR[q] = *(const float4*)&A[(long)(m0 + arow + q*32) * ldA + k0 + acol];
            #pragma unroll
            for (int q = 0; q < 4; q++)
                bR[q] = *(const float4*)&W[(long)(k0 + brow + q*8) * ldW + n0 + bcol];
        }
        #pragma unroll
        for (int kk = 0; kk < 32; kk += 8) {
            unsigned bf[4][2];
            #pragma unroll
            for (int nt = 0; nt < 4; nt++) {
                bf[nt][0] = Bs[cur][kk + tig][wn + nt*8 + g];
                bf[nt][1] = Bs[cur][kk + tig + 4][wn + nt*8 + g];
            }
            #pragma unroll
            for (int mt = 0; mt < MTW; mt++) {
                int r0 = wm + mt*16 + g;
                unsigned a0 = As[cur][r0][kk + tig];
                unsigned a1 = As[cur][r0 + 8][kk + tig];
                unsigned a2 = As[cur][r0][kk + tig + 4];
                unsigned a3 = As[cur][r0 + 8][kk + tig + 4];
                #pragma unroll
                for (int nt = 0; nt < 4; nt++)
                    mma_tf32(acc[mt][nt][0], acc[mt][nt][1], acc[mt][nt][2], acc[mt][nt][3],
                             a0, a1, a2, a3, bf[nt][0], bf[nt][1]);
            }
        }
        if (it + 1 < nIter) {
            #pragma unroll
            for (int q = 0; q < MTW; q++) {
                unsigned u[4] = {f2tf(aR[q].x), f2tf(aR[q].y), f2tf(aR[q].z), f2tf(aR[q].w)};
                *(uint4*)&As[nxt][arow + q*32][acol] = *(uint4*)u;
            }
            #pragma unroll
            for (int q = 0; q < 4; q++) {
                unsigned u[4] = {f2tf(bR[q].x), f2tf(bR[q].y), f2tf(bR[q].z), f2tf(bR[q].w)};
                *(uint4*)&Bs[nxt][brow + q*8][bcol] = *(uint4*)u;
            }
        }
        __syncthreads();
    }

    #pragma unroll
    for (int mt = 0; mt < MTW; mt++) {
        int row0 = m0 + wm + mt*16 + g;
        #pragma unroll
        for (int nt = 0; nt < 4; nt++) {
            int col = n0 + wn + nt*8 + 2*tig;
            float b0 = bias ? bias[col] : 0.f;
            float b1 = bias ? bias[col + 1] : 0.f;
            float v[4] = {acc[mt][nt][0] + b0, acc[mt][nt][1] + b1,
                          acc[mt][nt][2] + b0, acc[mt][nt][3] + b1};
            #pragma unroll
            for (int c = 0; c < 4; c++)
                if (ACT == 1) v[c] = v[c] > 0.f ? v[c] : 0.01f * v[c];
            *(float2*)&C[(long)row0 * ldC + col]       = make_float2(v[0], v[1]);
            *(float2*)&C[(long)(row0 + 8) * ldC + col] = make_float2(v[2], v[3]);
        }
    }

    if (FUSE) {
        const float* av = a_base + (z / Bq) * 256;
        #pragma unroll
        for (int mt = 0; mt < MTW; mt++) {
            int rl = wm + mt*16 + g;
            float p1a = 0.f, p2a = 0.f, p1b = 0.f, p2b = 0.f;
            #pragma unroll
            for (int nt = 0; nt < 4; nt++) {
                int col = wn + nt*8 + 2*tig;
                float a10 = av[col], a11 = av[col+1];
                float a20 = av[128+col], a21 = av[128+col+1];
                p1a += acc[mt][nt][0]*a10 + acc[mt][nt][1]*a11;
                p2a += acc[mt][nt][0]*a20 + acc[mt][nt][1]*a21;
                p1b += acc[mt][nt][2]*a10 + acc[mt][nt][3]*a11;
                p2b += acc[mt][nt][2]*a20 + acc[mt][nt][3]*a21;
            }
            atomicAdd(&s1p[rl], p1a);     atomicAdd(&s2p[rl], p2a);
            atomicAdd(&s1p[rl + 8], p1b); atomicAdd(&s2p[rl + 8], p2b);
        }
        __syncthreads();
        if (tid < MT) {
            long row = (long)z * Nn + m0 + tid;
            s1g[row] = s1p[tid];
            s2g[row] = s2p[tid];
        }
    }
}

// ============================================================================
// Fused att-GEMM, single-pass softmax:
//   E[i,j] = mask ? exp(lrelu(s1_i s2_j) - M_i) : 0,  M_i = |s1_i|*max|s2| (safe bound)
//   out    = act( (E @ Wh) * (1/rowsum_i) )
// Each E element is computed exactly once (one exp); rowsum accumulated during
// tile generation; normalization applied in the epilogue.
// Block tile 64 x 128, k-tile 32 over j. 256 threads. grid = (8, Zc).
// ============================================================================
template<int ACT>   // 1=lrelu 2=elu
__global__ void __launch_bounds__(256) attgemm_k(
    const float* __restrict__ Wh,
    const float* __restrict__ s1, const float* __restrict__ s2,
    const unsigned* __restrict__ maskbits,
    float* __restrict__ out, BOff co, int ldC)
{
    extern __shared__ unsigned dsm[];
    unsigned (*As)[64][36]  = (unsigned(*)[64][36])dsm;               // 2*64*36   = 4608
    unsigned (*Bs)[32][136] = (unsigned(*)[32][136])(dsm + 2*64*36);  // 2*32*136  = 8704
    float*    s2s = (float*)(dsm + 2*64*36 + 2*32*136);               // [512]
    float*    s1s = s2s + 512;                                        // [64]
    float*    zIs = s1s + 64;                                         // [64]
    unsigned* mw  = (unsigned*)(zIs + 64);                            // [64*16]
    __shared__ float red[8];
    __shared__ float s2max_sh;

    int z = blockIdx.y, b = z & 7;
    const float* whz = Wh + (long)z * Nn * NHID;
    float* outz = out + boff(co, z);
    int i0 = blockIdx.x * 64;

    int tid  = threadIdx.x;
    int lane = tid & 31, warp = tid >> 5;
    int wm = (warp >> 2) * 32, wn = (warp & 3) * 32;
    int g = lane >> 2, tig = lane & 3;
    int brow = tid >> 5, bcol = (tid & 31) * 4;

    // stage s2, s1, mask rows
    for (int t = tid; t < Nn; t += 256) s2s[t] = s2[(long)z * Nn + t];
    if (tid < 64) s1s[tid] = s1[(long)z * Nn + i0 + tid];
    for (int t = tid; t < 64*16; t += 256)
        mw[t] = maskbits[((long)b * Nn + i0 + (t >> 4)) * 16 + (t & 15)];
    __syncthreads();

    // block-wide S2max = max_j |s2_j|  (safe softmax shift bound)
    {
        float lm = 0.f;
        for (int t = tid; t < Nn; t += 256) lm = fmaxf(lm, fabsf(s2s[t]));
        #pragma unroll
        for (int off = 16; off; off >>= 1) lm = fmaxf(lm, __shfl_xor_sync(~0u, lm, off));
        if (!lane) red[warp] = lm;
        __syncthreads();
        if (tid == 0) {
            float m = red[0];
            #pragma unroll
            for (int k = 1; k < 8; k++) m = fmaxf(m, red[k]);
            s2max_sh = m;
        }
        __syncthreads();
    }
    float S2max = s2max_sh;

    // generator assignment: 4 threads per row, 8 j per k-tile each
    int grow = tid >> 2, gpart = tid & 3;
    float gs1 = s1s[grow];
    const unsigned* gmw = &mw[grow * 16];
    float gmi = fabsf(gs1) * S2max;      // >= lrelu(gs1*s2_j) for all j
    float rowsum = 0.f;

    // prologue: generate E tile 0, load Bs[0]
    {
        unsigned word = gmw[0];
        #pragma unroll
        for (int u = 0; u < 8; u++) {
            int jj = gpart*8 + u;
            float v = gs1 * s2s[jj];
            v = v > 0.f ? v : 0.01f * v;
            float p = ((word >> jj) & 1) ? __expf(v - gmi) : 0.f;
            rowsum += p;
            As[0][grow][jj] = f2tf(p);
        }
        float4 bR[4];
        #pragma unroll
        for (int q = 0; q < 4; q++)
            bR[q] = *(const float4*)&whz[(long)(brow + q*8) * NHID + bcol];
        #pragma unroll
        for (int q = 0; q < 4; q++) {
            unsigned u[4] = {f2tf(bR[q].x), f2tf(bR[q].y), f2tf(bR[q].z), f2tf(bR[q].w)};
            *(uint4*)&Bs[0][brow + q*8][bcol] = *(uint4*)u;
        }
    }
    __syncthreads();

    float acc[2][4][4];
    #pragma unroll
    for (int mt = 0; mt < 2; mt++)
        #pragma unroll
        for (int nt = 0; nt < 4; nt++)
            #pragma unroll
            for (int c = 0; c < 4; c++) acc[mt][nt][c] = 0.f;

    const int nIter = Nn / 32;   // 16
    for (int it = 0; it < nIter; it++) {
        int cur = it & 1, nxt = cur ^ 1;
        float4 bR[4];
        if (it + 1 < nIter) {
            int j0 = (it + 1) * 32;
            #pragma unroll
            for (int q = 0; q < 4; q++)
                bR[q] = *(const float4*)&whz[(long)(j0 + brow + q*8) * NHID + bcol];
        }
        #pragma unroll
        for (int kk = 0; kk < 32; kk += 8) {
            unsigned bf[4][2];
            #pragma unroll
            for (int nt = 0; nt < 4; nt++) {
                bf[nt][0] = Bs[cur][kk + tig][wn + nt*8 + g];
                bf[nt][1] = Bs[cur][kk + tig + 4][wn + nt*8 + g];
            }
            #pragma unroll
            for (int mt = 0; mt < 2; mt++) {
                int r0 = wm + mt*16 + g;
                unsigned a0 = As[cur][r0][kk + tig];
                unsigned a1 = As[cur][r0 + 8][kk + tig];
                unsigned a2 = As[cur][r0][kk + tig + 4];
                unsigned a3 = As[cur][r0 + 8][kk + tig + 4];
                #pragma unroll
                for (int nt = 0; nt < 4; nt++)
                    mma_tf32(acc[mt][nt][0], acc[mt][nt][1], acc[mt][nt][2], acc[mt][nt][3],
                             a0, a1, a2, a3, bf[nt][0], bf[nt][1]);
            }
        }
        if (it + 1 < nIter) {
            int j0 = (it + 1) * 32;
            unsigned word = gmw[j0 >> 5];
            #pragma unroll
            for (int u = 0; u < 8; u++) {
                int jj = gpart*8 + u;
                float v = gs1 * s2s[j0 + jj];
                v = v > 0.f ? v : 0.01f * v;
                float p = ((word >> jj) & 1) ? __expf(v - gmi) : 0.f;
                rowsum += p;
                As[nxt][grow][jj] = f2tf(p);
            }
            #pragma unroll
            for (int q = 0; q < 4; q++) {
                unsigned u[4] = {f2tf(bR[q].x), f2tf(bR[q].y), f2tf(bR[q].z), f2tf(bR[q].w)};
                *(uint4*)&Bs[nxt][brow + q*8][bcol] = *(uint4*)u;
            }
        }
        __syncthreads();
    }

    // reduce rowsum across the 4 generator threads of each row, publish 1/sum
    rowsum += __shfl_xor_sync(~0u, rowsum, 1);
    rowsum += __shfl_xor_sync(~0u, rowsum, 2);
    if (gpart == 0) zIs[grow] = rowsum > 0.f ? 1.f / rowsum : 0.f;
    __syncthreads();

    #pragma unroll
    for (int mt = 0; mt < 2; mt++) {
        int rl = wm + mt*16 + g;
        int row0 = i0 + rl;
        float sc0 = zIs[rl], sc1 = zIs[rl + 8];
        #pragma unroll
        for (int nt = 0; nt < 4; nt++) {
            int col = wn + nt*8 + 2*tig;
            float v[4] = {acc[mt][nt][0]*sc0, acc[mt][nt][1]*sc0,
                          acc[mt][nt][2]*sc1, acc[mt][nt][3]*sc1};
            #pragma unroll
            for (int c = 0; c < 4; c++) {
                if (ACT == 1) v[c] = v[c] > 0.f ? v[c] : 0.01f * v[c];
                else if (ACT == 2) v[c] = v[c] > 0.f ? v[c] : (expf(v[c]) - 1.f);
            }
            *(float2*)&outz[(long)row0 * ldC + col]       = make_float2(v[0], v[1]);
            *(float2*)&outz[(long)(row0 + 8) * ldC + col] = make_float2(v[2], v[3]);
        }
    }
}

// ============================================================================
// resh GEMM + bias + residual + LayerNorm fused.  32-row tiles -> grid 128.
// out = LN( hp2 @ rW + rb + res )
// ============================================================================
__global__ void __launch_bounds__(256) resh_ln_k(
    const float* __restrict__ A,          // hp2 [4096 x 512]
    const float* __restrict__ W,          // rW  [512 x 128]
    const float* __restrict__ bias,       // rb  [128]
    const float* __restrict__ res,        // residual [4096 x 128]
    float* __restrict__ out)              // [4096 x 128]
{
    extern __shared__ unsigned dsm[];
    unsigned (*As)[32][36]  = (unsigned(*)[32][36])dsm;               // 2*32*36 = 2304
    unsigned (*Bs)[32][136] = (unsigned(*)[32][136])(dsm + 2*32*36);  // 8704
    float*    S = (float*)(dsm + 2*32*36 + 2*32*136);                 // [32][132]

    int tid  = threadIdx.x;
    int lane = tid & 31, warp = tid >> 5;
    int wm = (warp >> 2) * 16, wn = (warp & 3) * 32;
    int g = lane >> 2, tig = lane & 3;
    int m0 = blockIdx.x * 32;

    int arow = tid >> 3, acol = (tid & 7) * 4;     // 32 rows x 8 col4 = 256 thr
    int brow = tid >> 5, bcol = (tid & 31) * 4;

    float4 aR, bR[4];
    aR = *(const float4*)&A[(long)(m0 + arow) * 512 + acol];
    #pragma unroll
    for (int q = 0; q < 4; q++)
        bR[q] = *(const float4*)&W[(long)(brow + q*8) * 128 + bcol];
    {
        unsigned u[4] = {f2tf(aR.x), f2tf(aR.y), f2tf(aR.z), f2tf(aR.w)};
        *(uint4*)&As[0][arow][acol] = *(uint4*)u;
    }
    #pragma unroll
    for (int q = 0; q < 4; q++) {
        unsigned u[4] = {f2tf(bR[q].x), f2tf(bR[q].y), f2tf(bR[q].z), f2tf(bR[q].w)};
        *(uint4*)&Bs[0][brow + q*8][bcol] = *(uint4*)u;
    }
    __syncthreads();

    float acc[4][4];
    #pragma unroll
    for (int nt = 0; nt < 4; nt++)
        #pragma unroll
        for (int c = 0; c < 4; c++) acc[nt][c] = 0.f;

    const int nIter = 512 / 32;  // 16
    for (int it = 0; it < nIter; it++) {
        int cur = it & 1, nxt = cur ^ 1;
        if (it + 1 < nIter) {
            int k0 = (it + 1) * 32;
            aR = *(const float4*)&A[(long)(m0 + arow) * 512 + k0 + acol];
            #pragma unroll
            for (int q = 0; q < 4; q++)
                bR[q] = *(const float4*)&W[(long)(k0 + brow + q*8) * 128 + bcol];
        }
        #pragma unroll
        for (int kk = 0; kk < 32; kk += 8) {
            unsigned bf[4][2];
            #pragma unroll
            for (int nt = 0; nt < 4; nt++) {
                bf[nt][0] = Bs[cur][kk + tig][wn + nt*8 + g];
                bf[nt][1] = Bs[cur][kk + tig + 4][wn + nt*8 + g];
            }
            int r0 = wm + g;
            unsigned a0 = As[cur][r0][kk + tig];
            unsigned a1 = As[cur][r0 + 8][kk + tig];
            unsigned a2 = As[cur][r0][kk + tig + 4];
            unsigned a3 = As[cur][r0 + 8][kk + tig + 4];
            #pragma unroll
            for (int nt = 0; nt < 4; nt++)
                mma_tf32(acc[nt][0], acc[nt][1], acc[nt][2], acc[nt][3],
                         a0, a1, a2, a3, bf[nt][0], bf[nt][1]);
        }
        if (it + 1 < nIter) {
            unsigned u[4] = {f2tf(aR.x), f2tf(aR.y), f2tf(aR.z), f2tf(aR.w)};
            *(uint4*)&As[nxt][arow][acol] = *(uint4*)u;
            #pragma unroll
            for (int q = 0; q < 4; q++) {
                unsigned w[4] = {f2tf(bR[q].x), f2tf(bR[q].y), f2tf(bR[q].z), f2tf(bR[q].w)};
                *(uint4*)&Bs[nxt][brow + q*8][bcol] = *(uint4*)w;
            }
        }
        __syncthreads();
    }

    // stage acc + bias into S
    {
        int rl = wm + g;
        #pragma unroll
        for (int nt = 0; nt < 4; nt++) {
            int col = wn + nt*8 + 2*tig;
            float b0 = bias[col], b1 = bias[col + 1];
            S[rl*132 + col]       = acc[nt][0] + b0;
            S[rl*132 + col+1]     = acc[nt][1] + b1;
            S[(rl+8)*132 + col]   = acc[nt][2] + b0;
            S[(rl+8)*132 + col+1] = acc[nt][3] + b1;
        }
    }
    __syncthreads();

    // LN with residual: 8 threads per row, 16 cols each
    {
        int row = tid >> 3, part = tid & 7;
        int c0 = part * 16;
        float v[16];
        float s = 0.f;
        #pragma unroll
        for (int q = 0; q < 4; q++) {
            float4 r4 = *(const float4*)&res[(long)(m0 + row) * 128 + c0 + q*4];
            v[q*4+0] = S[row*132 + c0 + q*4+0] + r4.x;
            v[q*4+1] = S[row*132 + c0 + q*4+1] + r4.y;
            v[q*4+2] = S[row*132 + c0 + q*4+2] + r4.z;
            v[q*4+3] = S[row*132 + c0 + q*4+3] + r4.w;
            s += v[q*4+0] + v[q*4+1] + v[q*4+2] + v[q*4+3];
        }
        s += __shfl_xor_sync(~0u, s, 1);
        s += __shfl_xor_sync(~0u, s, 2);
        s += __shfl_xor_sync(~0u, s, 4);
        float mean = s * (1.f/128.f);
        float var = 0.f;
        #pragma unroll
        for (int k = 0; k < 16; k++) { float d = v[k] - mean; var += d*d; }
        var += __shfl_xor_sync(~0u, var, 1);
        var += __shfl_xor_sync(~0u, var, 2);
        var += __shfl_xor_sync(~0u, var, 4);
        float inv = rsqrtf(var * (1.f/128.f) + 1e-5f);
        #pragma unroll
        for (int q = 0; q < 4; q++) {
            float4 o4 = make_float4((v[q*4+0]-mean)*inv, (v[q*4+1]-mean)*inv,
                                    (v[q*4+2]-mean)*inv, (v[q*4+3]-mean)*inv);
            *(float4*)&out[(long)(m0 + row) * 128 + c0 + q*4] = o4;
        }
    }
}

// ============================================================================
// FEL megakernel: the whole 6-GEMM + 2-LN MLP, row-local, one launch.
// grid 64 blocks x 64 rows, activations in smem.  LDS0 = 260 (16B-aligned rows).
// ============================================================================
#define LDS0 260

__device__ __forceinline__ void fel_layer(
    const float* __restrict__ Sin,        // smem act, ld LDS0
    const float* __restrict__ W,          // global [K x Nout]
    const float* __restrict__ bias,       // global [Nout]
    int K, int Nout, bool act,
    float* __restrict__ Sout, int ldOut,  // smem
    unsigned* __restrict__ Wb)            // smem [32*136]
{
    int tid  = threadIdx.x;
    int lane = tid & 31, warp = tid >> 5;
    int wm = (warp >> 2) * 32, wn = (warp & 3) * 32;
    int g = lane >> 2, tig = lane & 3;
    int brow = tid >> 5, bcol = (tid & 31) * 4;

    for (int nc = 0; nc < Nout; nc += 128) {
        float acc[2][4][4];
        #pragma unroll
        for (int mt = 0; mt < 2; mt++)
            #pragma unroll
            for (int nt = 0; nt < 4; nt++)
                #pragma unroll
                for (int c = 0; c < 4; c++) acc[mt][nt][c] = 0.f;

        for (int k0 = 0; k0 < K; k0 += 32) {
            #pragma unroll
            for (int q = 0; q < 4; q++) {
                float4 v = *(const float4*)&W[(long)(k0 + brow + q*8) * Nout + nc + bcol];
                unsigned u[4] = {f2tf(v.x), f2tf(v.y), f2tf(v.z), f2tf(v.w)};
                *(uint4*)&Wb[(brow + q*8)*136 + bcol] = *(uint4*)u;
            }
            __syncthreads();
            #pragma unroll
            for (int kk = 0; kk < 32; kk += 8) {
                unsigned bf[4][2];
                #pragma unroll
                for (int nt = 0; nt < 4; nt++) {
                    bf[nt][0] = Wb[(kk + tig)*136 + wn + nt*8 + g];
                    bf[nt][1] = Wb[(kk + tig + 4)*136 + wn + nt*8 + g];
                }
                #pragma unroll
                for (int mt = 0; mt < 2; mt++) {
                    int r0 = wm + mt*16 + g;
                    unsigned a0 = f2tf(Sin[r0*LDS0 + k0 + kk + tig]);
                    unsigned a1 = f2tf(Sin[(r0+8)*LDS0 + k0 + kk + tig]);
                    unsigned a2 = f2tf(Sin[r0*LDS0 + k0 + kk + tig + 4]);
                    unsigned a3 = f2tf(Sin[(r0+8)*LDS0 + k0 + kk + tig + 4]);
                    #pragma unroll
                    for (int nt = 0; nt < 4; nt++)
                        mma_tf32(acc[mt][nt][0], acc[mt][nt][1], acc[mt][nt][2], acc[mt][nt][3],
                                 a0, a1, a2, a3, bf[nt][0], bf[nt][1]);
                }
            }
            __syncthreads();
        }
        #pragma unroll
        for (int mt = 0; mt < 2; mt++) {
            int r0 = wm + mt*16 + g;
            #pragma unroll
            for (int nt = 0; nt < 4; nt++) {
                int col = nc + wn + nt*8 + 2*tig;
                float b0 = bias[col], b1 = bias[col+1];
                float v0 = acc[mt][nt][0]+b0, v1 = acc[mt][nt][1]+b1;
                float v2 = acc[mt][nt][2]+b0, v3 = acc[mt][nt][3]+b1;
                if (act) {
                    v0 = v0 > 0.f ? v0 : 0.01f*v0; v1 = v1 > 0.f ? v1 : 0.01f*v1;
                    v2 = v2 > 0.f ? v2 : 0.01f*v2; v3 = v3 > 0.f ? v3 : 0.01f*v3;
                }
                Sout[r0*ldOut + col] = v0;     Sout[r0*ldOut + col+1] = v1;
                Sout[(r0+8)*ldOut + col] = v2; Sout[(r0+8)*ldOut + col+1] = v3;
            }
        }
        __syncthreads();
    }
}

__device__ __forceinline__ void fel_ln(
    const float* __restrict__ Sh, int ldH,
    const float* __restrict__ Sres, int ldR,
    float* __restrict__ dst, int ldD)
{
    int tid = threadIdx.x;
    int row = tid >> 2, part = tid & 3;
    int c0 = part * 32;
    float v[32];
    float s = 0.f;
    #pragma unroll
    for (int k = 0; k < 32; k++) {
        v[k] = Sh[row*ldH + c0 + k] + Sres[row*ldR + c0 + k];
        s += v[k];
    }
    s += __shfl_xor_sync(~0u, s, 1);
    s += __shfl_xor_sync(~0u, s, 2);
    float mean = s * (1.f/128.f);
    float var = 0.f;
    #pragma unroll
    for (int k = 0; k < 32; k++) { float d = v[k]-mean; var += d*d; }
    var += __shfl_xor_sync(~0u, var, 1);
    var += __shfl_xor_sync(~0u, var, 2);
    float inv = rsqrtf(var * (1.f/128.f) + 1e-5f);
    #pragma unroll
    for (int k = 0; k < 32; k++)
        dst[row*ldD + c0 + k] = (v[k]-mean)*inv;
    __syncthreads();
}

__global__ void __launch_bounds__(256) fel_k(
    const float* __restrict__ x,
    const float* __restrict__ f1w1, const float* __restrict__ f1b1,
    const float* __restrict__ f1w2, const float* __restrict__ f1b2,
    const float* __restrict__ f2w1, const float* __restrict__ f2b1,
    const float* __restrict__ f2w2, const float* __restrict__ f2b2,
    const float* __restrict__ f3w1, const float* __restrict__ f3b1,
    const float* __restrict__ f3w2, const float* __restrict__ f3b2,
    float* __restrict__ out)
{
    extern __shared__ float fsm[];
    float* S0 = fsm;                    // [64][LDS0]
    float* S1 = S0 + 64*LDS0;           // [64][LDS0]
    float* S2 = S1 + 64*LDS0;           // [64][132]
    unsigned* Wb = (unsigned*)(S2 + 64*132);   // [32*136]

    int tid = threadIdx.x;
    int m0 = blockIdx.x * 64;

    // load x rows (64 x 32)
    for (int i = tid; i < 64*32/4; i += 256) {
        float4 v = *(const float4*)&x[(long)m0*32 + i*4];
        int row = (i*4) >> 5, col = (i*4) & 31;
        *(float4*)&S0[row*LDS0 + col] = v;
    }
    __syncthreads();

    fel_layer(S0, f1w1, f1b1, 32,  128, true,  S1, LDS0, Wb);
    fel_layer(S1, f1w2, f1b2, 128, 128, true,  S0, LDS0, Wb);   // res in S0
    fel_layer(S0, f2w1, f2b1, 128, 256, true,  S1, LDS0, Wb);
    fel_layer(S1, f2w2, f2b2, 256, 128, true,  S2, 132, Wb);
    fel_ln(S2, 132, S0, LDS0, S1, LDS0);                         // x2 in S1
    fel_layer(S1, f3w1, f3b1, 128, 256, true,  S0, LDS0, Wb);
    fel_layer(S0, f3w2, f3b2, 256, 128, false, S2, 132, Wb);
    fel_ln(S2, 132, S1, LDS0, out + (long)m0*128, 128);
}

// ---------------- adjacency -> packed bitmask (normal + transposed) ----------------
__global__ void maskbuild_k(const int* __restrict__ adj,
                            unsigned* __restrict__ mb, unsigned* __restrict__ mbT)
{
    int i = blockIdx.x, b = blockIdx.y, j = threadIdx.x;
    int lane = j & 31, w = j >> 5;
    unsigned bit  = adj[((long)b * Nn + i) * Nn + j] > 0;
    unsigned word = __ballot_sync(~0u, bit);
    if (!lane) mb[((long)b * Nn + i) * 16 + w] = word;
    unsigned bitT  = adj[((long)b * Nn + j) * Nn + i] > 0;
    unsigned wordT = __ballot_sync(~0u, bitT);
    if (!lane) mbT[((long)b * Nn + i) * 16 + w] = wordT;
}

// ---------------- final: out[b] = mean_n concat(hf,ht) . proj_W + proj_b ----------------
__global__ void final_k(const float* __restrict__ hf, const float* __restrict__ ht,
                        const float* __restrict__ pW, const float* __restrict__ pb,
                        float* __restrict__ out)
{
    int b = blockIdx.x, t = threadIdx.x;
    const float* src = (t < 128) ? hf : ht;
    int f = t & 127;
    float w = pW[t];
    float acc = 0.f;
    for (int n = 0; n < Nn; n++) acc += src[((long)b * Nn + n) * 128 + f];
    acc *= w;
    __shared__ float red[8];
    for (int off = 16; off; off >>= 1) acc += __shfl_xor_sync(~0u, acc, off);
    if ((t & 31) == 0) red[t >> 5] = acc;
    __syncthreads();
    if (t == 0) {
        float s = 0.f;
        #pragma unroll
        for (int k = 0; k < 8; k++) s += red[k];
        out[b] = s / (float)Nn + pb[0];
    }
}

// ---------------- host orchestration ----------------
static inline BOff Z()            { return BOff{1, 0, 0}; }
static inline BOff perZ(long s)   { return BOff{1, 0, s}; }

#define SMEMG    ((2*64*36 + 2*32*136) * 4)                               // 53248
#define SMEMATT  ((2*64*36 + 2*32*136 + 512 + 64 + 64) * 4 + 64*16*4)     // 59904
#define SMEMRESH ((2*32*36 + 2*32*136) * 4 + 32*132*4)                    // 60928
#define SMEMFEL  ((64*LDS0*2 + 64*132) * 4 + 32*136*4)                    // 184320

static void attn_block(const float* in, float* out, int blk,
                       const unsigned* mb,
                       const float* att_W, const float* att_a,
                       const float* resh_W, const float* resh_b,
                       float* Wh, float* hp2, float* s1, float* s2)
{
    const float* Wblk = att_W  + (long)blk * NHEADS * 128 * 128;
    const float* ablk = att_a  + (long)blk * NHEADS * 256;
    const float* rW   = resh_W + (long)blk * 512 * 128;
    const float* rb   = resh_b + (long)blk * 128;
    const int Zc = NHEADS * Bq;   // 32

    gemm32_k<0,true><<<dim3(1, 8, Zc), 256, SMEMG>>>(
        in,   BOff{Bq, (long)Nn*128, 0}, 128,
        Wblk, BOff{Bq, 0, 128*128},      128,
        nullptr, Z(),
        Wh, perZ((long)Nn*128), 128, 128,
        s1, s2, ablk);
    attgemm_k<2><<<dim3(8, Zc), 256, SMEMATT>>>(
        Wh, s1, s2, mb, hp2, BOff{Bq, (long)Nn*512, 128}, 512);
    resh_ln_k<<<128, 256, SMEMRESH>>>(hp2, rW, rb, in, out);
}

static void out_gat(const float* in, float* dst, int widx,
                    const unsigned* mb,
                    const float* out_W, const float* out_a,
                    float* Wh, float* s1, float* s2)
{
    const float* Wblk = out_W + (long)widx * 128 * 128;
    const float* ablk = out_a + (long)widx * 256;
    const int Zc = Bq;

    gemm32_k<0,true><<<dim3(1, 8, Zc), 256, SMEMG>>>(
        in,   perZ((long)Nn*128), 128,
        Wblk, Z(),                128,
        nullptr, Z(),
        Wh, perZ((long)Nn*128), 128, 128,
        s1, s2, ablk);
    attgemm_k<1><<<dim3(8, Zc), 256, SMEMATT>>>(
        Wh, s1, s2, mb, dst, perZ((long)Nn*128), 128);
}

extern "C" void kernel_launch(void* const* d_in, const int* in_sizes, int n_in,
                              void* d_out, int out_size)
{
    const float* x      = (const float*)d_in[0];
    const int*   adj    = (const int*)  d_in[1];
    const float* f1w1 = (const float*)d_in[3];  const float* f1b1 = (const float*)d_in[4];
    const float* f1w2 = (const float*)d_in[5];  const float* f1b2 = (const float*)d_in[6];
    const float* f2w1 = (const float*)d_in[7];  const float* f2b1 = (const float*)d_in[8];
    const float* f2w2 = (const float*)d_in[9];  const float* f2b2 = (const float*)d_in[10];
    const float* f3w1 = (const float*)d_in[11]; const float* f3b1 = (const float*)d_in[12];
    const float* f3w2 = (const float*)d_in[13]; const float* f3b2 = (const float*)d_in[14];
    const float* att_W  = (const float*)d_in[15];
    const float* att_a  = (const float*)d_in[16];
    const float* resh_W = (const float*)d_in[17];
    const float* resh_b = (const float*)d_in[18];
    const float* out_W  = (const float*)d_in[19];
    const float* out_a  = (const float*)d_in[20];
    const float* proj_W = (const float*)d_in[21];
    const float* proj_b = (const float*)d_in[22];
    float* out = (float*)d_out;

    static bool attr_done = false;
    if (!attr_done) {
        cudaFuncSetAttribute(gemm32_k<0,false>, cudaFuncAttributeMaxDynamicSharedMemorySize, SMEMG);
        cudaFuncSetAttribute(gemm32_k<0,true>,  cudaFuncAttributeMaxDynamicSharedMemorySize, SMEMG);
        cudaFuncSetAttribute(attgemm_k<1>, cudaFuncAttributeMaxDynamicSharedMemorySize, SMEMATT);
        cudaFuncSetAttribute(attgemm_k<2>, cudaFuncAttributeMaxDynamicSharedMemorySize, SMEMATT);
        cudaFuncSetAttribute(resh_ln_k, cudaFuncAttributeMaxDynamicSharedMemorySize, SMEMRESH);
        cudaFuncSetAttribute(fel_k, cudaFuncAttributeMaxDynamicSharedMemorySize, SMEMFEL);
        attr_done = true;
    }

    float *bufA, *bufB, *hp2, *Wh, *s1, *s2, *hf, *ht;
    unsigned *mask, *maskT;
    cudaGetSymbolAddress((void**)&bufA, g_bufA);
    cudaGetSymbolAddress((void**)&bufB, g_bufB);
    cudaGetSymbolAddress((void**)&hp2,  g_hp2);
    cudaGetSymbolAddress((void**)&Wh,   g_Wh);
    cudaGetSymbolAddress((void**)&s1,   g_s1);
    cudaGetSymbolAddress((void**)&s2,   g_s2);
    cudaGetSymbolAddress((void**)&hf,   g_hf);
    cudaGetSymbolAddress((void**)&ht,   g_ht);
    cudaGetSymbolAddress((void**)&mask,  g_mask);
    cudaGetSymbolAddress((void**)&maskT, g_maskT);

    // masks
    maskbuild_k<<<dim3(Nn, Bq), 512>>>(adj, mask, maskT);

    // ---- FEL (single megakernel) ----
    fel_k<<<64, 256, SMEMFEL>>>(x, f1w1, f1b1, f1w2, f1b2,
                                f2w1, f2b1, f2w2, f2b2,
                                f3w1, f3b1, f3w2, f3b2, bufA);

    // ---- forward chain (mask) ----
    for (int i = 0; i < 3; i++)
        attn_block(bufA, bufA, i, mask, att_W, att_a, resh_W, resh_b, Wh, hp2, s1, s2);
    out_gat(bufA, hf, 0, mask, out_W, out_a, Wh, s1, s2);

    // ---- transposed chain (mask_t), seeded from hf ----
    attn_block(hf,   bufB, 3, maskT, att_W, att_a, resh_W, resh_b, Wh, hp2, s1, s2);
    attn_block(bufB, bufB, 4, maskT, att_W, att_a, resh_W, resh_b, Wh, hp2, s1, s2);
    attn_block(bufB, bufB, 5, maskT, att_W, att_a, resh_W, resh_b, Wh, hp2, s1, s2);
    out_gat(bufB, ht, 1, maskT, out_W, out_a, Wh, s1, s2);

    // ---- readout ----
    final_k<<<Bq, 256>>>(hf, ht, proj_W, proj_b, out);
    (void)in_sizes; (void)n_in; (void)out_size;
}